// round 1
// baseline (speedup 1.0000x reference)
#include <cuda_runtime.h>
#include <math.h>

#define BSZ   4
#define TSEQ  1024
#define CDIM  1024
#define NHEAD 16
#define DHEAD 64

// Scratch (allocation-free: __device__ globals)
__device__ float g_qkv[BSZ * TSEQ * 3 * CDIM];   // [B,T,3C]
__device__ float g_y[BSZ * TSEQ * CDIM];         // [B,T,C] head-interleaved

// ---------------------------------------------------------------------------
// fp32 SGEMM: C[M,N] = A[M,K] @ B[K,N], 128x128x16 tiles, 256 thr, 8x8 micro
// ---------------------------------------------------------------------------
__global__ void __launch_bounds__(256) sgemm_kernel(
    const float* __restrict__ A, const float* __restrict__ B,
    float* __restrict__ C, int M, int N, int K) {
  __shared__ float As[16][132];   // transposed A tile, padded
  __shared__ float Bs[16][132];

  const int tid  = threadIdx.x;
  const int brow = blockIdx.y * 128;
  const int bcol = blockIdx.x * 128;
  const int ty = tid >> 4, tx = tid & 15;

  float acc[8][8];
#pragma unroll
  for (int i = 0; i < 8; i++)
#pragma unroll
    for (int j = 0; j < 8; j++) acc[i][j] = 0.f;

  for (int k0 = 0; k0 < K; k0 += 16) {
    // load A tile 128x16 (store transposed)
#pragma unroll
    for (int i = 0; i < 2; i++) {
      int id = tid + i * 256;
      int r  = id >> 2;
      int c4 = (id & 3) * 4;
      float4 v = *(const float4*)&A[(size_t)(brow + r) * K + k0 + c4];
      As[c4 + 0][r] = v.x; As[c4 + 1][r] = v.y;
      As[c4 + 2][r] = v.z; As[c4 + 3][r] = v.w;
    }
    // load B tile 16x128
#pragma unroll
    for (int i = 0; i < 2; i++) {
      int id = tid + i * 256;
      int r  = id >> 5;
      int c4 = (id & 31) * 4;
      *(float4*)&Bs[r][c4] = *(const float4*)&B[(size_t)(k0 + r) * N + bcol + c4];
    }
    __syncthreads();
#pragma unroll
    for (int kk = 0; kk < 16; kk++) {
      float a[8], b[8];
      *(float4*)&a[0] = *(float4*)&As[kk][ty * 8];
      *(float4*)&a[4] = *(float4*)&As[kk][ty * 8 + 4];
      *(float4*)&b[0] = *(float4*)&Bs[kk][tx * 8];
      *(float4*)&b[4] = *(float4*)&Bs[kk][tx * 8 + 4];
#pragma unroll
      for (int i = 0; i < 8; i++)
#pragma unroll
        for (int j = 0; j < 8; j++) acc[i][j] += a[i] * b[j];
    }
    __syncthreads();
  }
#pragma unroll
  for (int i = 0; i < 8; i++) {
    size_t r = (size_t)(brow + ty * 8 + i) * N + bcol + tx * 8;
    *(float4*)&C[r]     = make_float4(acc[i][0], acc[i][1], acc[i][2], acc[i][3]);
    *(float4*)&C[r + 4] = make_float4(acc[i][4], acc[i][5], acc[i][6], acc[i][7]);
  }
}

// ---------------------------------------------------------------------------
// Flash attention with relative-position bias on scores and values.
// One block per (b, h, 64-row q tile). 256 threads, 4x4 microtiles.
// Key facts:
//  - smem rel row index for a (t_loc, s_loc) pair is t_loc - s_loc + 63,
//    independent of the block-diagonal offset (diff folds into the staged rows)
//  - value-side RPE folds into P:  O += P[t,s] * (V[s,:] + embv[t-s,:])
// ---------------------------------------------------------------------------
#define SM_STRIDE 68
#define ATT_SMEM_FLOATS (4 * 64 * SM_STRIDE + 2 * 128 * SM_STRIDE + 3 * 64)
#define ATT_SMEM_BYTES  (ATT_SMEM_FLOATS * 4)

__global__ void __launch_bounds__(256) attn_kernel(
    const float* __restrict__ qkv, const float* __restrict__ embk,
    const float* __restrict__ embv, float* __restrict__ y) {
  extern __shared__ float sm[];
  float* Qs  = sm;                       // 64 x 68
  float* Ks  = Qs + 64 * SM_STRIDE;      // 64 x 68  (pre-scaled by 1/sqrt(d))
  float* Vs  = Ks + 64 * SM_STRIDE;      // 64 x 68
  float* Ss  = Vs + 64 * SM_STRIDE;      // 64 x 68  scores -> probs
  float* Ek  = Ss + 64 * SM_STRIDE;      // 128 x 68 staged embk rows
  float* Ev  = Ek + 128 * SM_STRIDE;     // 128 x 68 staged embv rows
  float* m_s = Ev + 128 * SM_STRIDE;     // 64
  float* l_s = m_s + 64;                 // 64
  float* cf  = l_s + 64;                 // 64

  const int tid = threadIdx.x;
  const int tb = blockIdx.x, h = blockIdx.y, b = blockIdx.z;
  const int t0 = tb * 64;
  const int ty = tid >> 4, tx = tid & 15;
  const int tloc = ty * 4;   // micro-tile row base (t within block)
  const int cloc = tx * 4;   // micro-tile col base (s in S phase, e in O phase)

  // Load Q tile
#pragma unroll
  for (int i = 0; i < 16; i++) {
    int lin = i * 256 + tid;
    int t = lin >> 6, kk = lin & 63;
    Qs[t * SM_STRIDE + kk] = qkv[(b * TSEQ + t0 + t) * (3 * CDIM) + h * 64 + kk];
  }
  if (tid < 64) { m_s[tid] = -1e30f; l_s[tid] = 0.f; }

  float accO[4][4];
#pragma unroll
  for (int i = 0; i < 4; i++)
#pragma unroll
    for (int j = 0; j < 4; j++) accO[i][j] = 0.f;

  for (int sb = 0; sb <= tb; sb++) {
    const int s0 = sb * 64;
    const int diff = t0 - s0;
    __syncthreads();   // previous iteration's smem reads done; safe to overwrite

    // stage K (pre-scaled), V
#pragma unroll
    for (int i = 0; i < 16; i++) {
      int lin = i * 256 + tid;
      int s = lin >> 6, kk = lin & 63;
      int off = (b * TSEQ + s0 + s) * (3 * CDIM) + h * 64 + kk;
      Ks[s * SM_STRIDE + kk] = qkv[off + CDIM] * 0.125f;  // 1/sqrt(64)
      Vs[s * SM_STRIDE + kk] = qkv[off + 2 * CDIM];
    }
    // stage rel rows: row j holds embk/embv[diff-63+j] (zero if out of range)
#pragma unroll
    for (int i = 0; i < 32; i++) {
      int lin = i * 256 + tid;
      int j = lin >> 6, kk = lin & 63;
      int rel = diff - 63 + j;
      bool ok = (rel >= 0) && (rel < TSEQ);
      Ek[j * SM_STRIDE + kk] = ok ? embk[rel * 64 + kk] : 0.f;
      Ev[j * SM_STRIDE + kk] = ok ? embv[rel * 64 + kk] : 0.f;
    }
    __syncthreads();

    // ---- S phase: S[t,s] = q . (k_scaled + embk[t-s]) ----
    float acc[4][4];
#pragma unroll
    for (int i = 0; i < 4; i++)
#pragma unroll
      for (int j = 0; j < 4; j++) acc[i][j] = 0.f;

    const int ebase = tloc - cloc + 63;   // rel-row base; only 7 distinct rows
#pragma unroll 4
    for (int kk = 0; kk < 64; kk += 4) {
      float4 qv[4], kv[4], ev[7];
#pragma unroll
      for (int i = 0; i < 4; i++) qv[i] = *(float4*)&Qs[(tloc + i) * SM_STRIDE + kk];
#pragma unroll
      for (int j = 0; j < 4; j++) kv[j] = *(float4*)&Ks[(cloc + j) * SM_STRIDE + kk];
#pragma unroll
      for (int m = 0; m < 7; m++) ev[m] = *(float4*)&Ek[(ebase - 3 + m) * SM_STRIDE + kk];
#pragma unroll
      for (int i = 0; i < 4; i++)
#pragma unroll
        for (int j = 0; j < 4; j++) {
          float4 q4 = qv[i], kb = kv[j], eb = ev[i - j + 3];
          acc[i][j] += q4.x * (kb.x + eb.x) + q4.y * (kb.y + eb.y)
                     + q4.z * (kb.z + eb.z) + q4.w * (kb.w + eb.w);
        }
    }
    // write scores with causal mask
#pragma unroll
    for (int i = 0; i < 4; i++)
#pragma unroll
      for (int j = 0; j < 4; j++) {
        bool masked = (sb == tb) && (cloc + j > tloc + i);
        Ss[(tloc + i) * SM_STRIDE + cloc + j] = masked ? -1e30f : acc[i][j];
      }
    __syncthreads();

    // ---- online softmax (row-per-thread) ----
    if (tid < 64) {
      float mold = m_s[tid];
      float mx = mold;
      float* row = &Ss[tid * SM_STRIDE];
#pragma unroll 8
      for (int s = 0; s < 64; s++) mx = fmaxf(mx, row[s]);
      float c = __expf(mold - mx);
      float sum = 0.f;
#pragma unroll 8
      for (int s = 0; s < 64; s++) {
        float p = __expf(row[s] - mx);
        row[s] = p;
        sum += p;
      }
      m_s[tid] = mx;
      l_s[tid] = l_s[tid] * c + sum;
      cf[tid] = c;
    }
    __syncthreads();

    // ---- O phase: O[t,e] += P[t,s] * (V[s,e] + embv[t-s][e]) ----
    float cfi[4];
#pragma unroll
    for (int i = 0; i < 4; i++) {
      cfi[i] = cf[tloc + i];
#pragma unroll
      for (int j = 0; j < 4; j++) accO[i][j] *= cfi[i];
    }
#pragma unroll 4
    for (int s = 0; s < 64; s++) {
      float4 v4 = *(float4*)&Vs[s * SM_STRIDE + cloc];
      float p[4];
#pragma unroll
      for (int i = 0; i < 4; i++) p[i] = Ss[(tloc + i) * SM_STRIDE + s];
#pragma unroll
      for (int i = 0; i < 4; i++) {
        float4 e4 = *(float4*)&Ev[(tloc + i - s + 63) * SM_STRIDE + cloc];
        accO[i][0] += p[i] * (v4.x + e4.x);
        accO[i][1] += p[i] * (v4.y + e4.y);
        accO[i][2] += p[i] * (v4.z + e4.z);
        accO[i][3] += p[i] * (v4.w + e4.w);
      }
    }
  }

  // epilogue: normalize and write y[b, t, h*64 + e]
#pragma unroll
  for (int i = 0; i < 4; i++) {
    float linv = 1.f / l_s[tloc + i];
    float4 o = make_float4(accO[i][0] * linv, accO[i][1] * linv,
                           accO[i][2] * linv, accO[i][3] * linv);
    *(float4*)&y[(b * TSEQ + t0 + tloc + i) * CDIM + h * 64 + cloc] = o;
  }
}

// ---------------------------------------------------------------------------
extern "C" void kernel_launch(void* const* d_in, const int* in_sizes, int n_in,
                              void* d_out, int out_size) {
  const float* x      = (const float*)d_in[0];
  const float* w_attn = (const float*)d_in[1];
  const float* w_proj = (const float*)d_in[2];
  const float* embk   = (const float*)d_in[3];
  const float* embv   = (const float*)d_in[4];
  float* out = (float*)d_out;

  float* qkv; cudaGetSymbolAddress((void**)&qkv, g_qkv);
  float* y;   cudaGetSymbolAddress((void**)&y, g_y);

  // QKV: [4096,1024] @ [1024,3072]
  sgemm_kernel<<<dim3(3072 / 128, 4096 / 128), 256>>>(x, w_attn, qkv,
                                                      BSZ * TSEQ, 3 * CDIM, CDIM);

  cudaFuncSetAttribute(attn_kernel, cudaFuncAttributeMaxDynamicSharedMemorySize,
                       ATT_SMEM_BYTES);
  attn_kernel<<<dim3(TSEQ / 64, NHEAD, BSZ), 256, ATT_SMEM_BYTES>>>(qkv, embk,
                                                                    embv, y);

  // Projection: [4096,1024] @ [1024,1024]
  sgemm_kernel<<<dim3(CDIM / 128, 4096 / 128), 256>>>(y, w_proj, out,
                                                      BSZ * TSEQ, CDIM, CDIM);
}

// round 3
// speedup vs baseline: 1.0122x; 1.0122x over previous
#include <cuda_runtime.h>
#include <math.h>

#define BSZ   4
#define TSEQ  1024
#define CDIM  1024
#define NHEAD 16
#define DHEAD 64

// Scratch (allocation-free: __device__ globals)
__device__ float g_qkv[BSZ * TSEQ * 3 * CDIM];   // [B,T,3C]
__device__ float g_y[BSZ * TSEQ * CDIM];         // [B,T,C] head-interleaved

// ---------------------------------------------------------------------------
// fp32 SGEMM: C[M,N] = A[M,K] @ B[K,N], 128x128x16 tiles, 256 thr, 8x8 micro,
// double-buffered smem (1 sync per k-tile, global loads prefetched to regs)
// ---------------------------------------------------------------------------
__global__ void __launch_bounds__(256) sgemm_kernel(
    const float* __restrict__ A, const float* __restrict__ B,
    float* __restrict__ C, int M, int N, int K) {
  __shared__ float As[2][16][132];   // transposed A tile, padded
  __shared__ float Bs[2][16][132];

  const int tid  = threadIdx.x;
  const int brow = blockIdx.y * 128;
  const int bcol = blockIdx.x * 128;
  const int ty = tid >> 4, tx = tid & 15;

  // A-load lane mapping: 2 x (row r, 4-col chunk c4)
  const int ar0 = tid >> 2,          ac0 = (tid & 3) * 4;
  const int ar1 = (tid + 256) >> 2,  ac1 = ((tid + 256) & 3) * 4;
  const int br0 = tid >> 5,          bc0 = (tid & 31) * 4;
  const int br1 = (tid + 256) >> 5,  bc1 = ((tid + 256) & 31) * 4;

  float acc[8][8];
#pragma unroll
  for (int i = 0; i < 8; i++)
#pragma unroll
    for (int j = 0; j < 8; j++) acc[i][j] = 0.f;

  // prologue: load k-tile 0 into buffer 0
  {
    float4 a0 = *(const float4*)&A[(size_t)(brow + ar0) * K + ac0];
    float4 a1 = *(const float4*)&A[(size_t)(brow + ar1) * K + ac1];
    As[0][ac0 + 0][ar0] = a0.x; As[0][ac0 + 1][ar0] = a0.y;
    As[0][ac0 + 2][ar0] = a0.z; As[0][ac0 + 3][ar0] = a0.w;
    As[0][ac1 + 0][ar1] = a1.x; As[0][ac1 + 1][ar1] = a1.y;
    As[0][ac1 + 2][ar1] = a1.z; As[0][ac1 + 3][ar1] = a1.w;
    *(float4*)&Bs[0][br0][bc0] = *(const float4*)&B[(size_t)br0 * N + bcol + bc0];
    *(float4*)&Bs[0][br1][bc1] = *(const float4*)&B[(size_t)br1 * N + bcol + bc1];
  }
  __syncthreads();

  int buf = 0;
  for (int k0 = 0; k0 < K; k0 += 16) {
    const bool has_next = (k0 + 16) < K;
    float4 pa0, pa1, pb0, pb1;
    if (has_next) {
      pa0 = *(const float4*)&A[(size_t)(brow + ar0) * K + k0 + 16 + ac0];
      pa1 = *(const float4*)&A[(size_t)(brow + ar1) * K + k0 + 16 + ac1];
      pb0 = *(const float4*)&B[(size_t)(k0 + 16 + br0) * N + bcol + bc0];
      pb1 = *(const float4*)&B[(size_t)(k0 + 16 + br1) * N + bcol + bc1];
    }
#pragma unroll
    for (int kk = 0; kk < 16; kk++) {
      float a[8], b[8];
      *(float4*)&a[0] = *(float4*)&As[buf][kk][ty * 8];
      *(float4*)&a[4] = *(float4*)&As[buf][kk][ty * 8 + 4];
      *(float4*)&b[0] = *(float4*)&Bs[buf][kk][tx * 8];
      *(float4*)&b[4] = *(float4*)&Bs[buf][kk][tx * 8 + 4];
#pragma unroll
      for (int i = 0; i < 8; i++)
#pragma unroll
        for (int j = 0; j < 8; j++) acc[i][j] += a[i] * b[j];
    }
    if (has_next) {
      int nb = buf ^ 1;
      As[nb][ac0 + 0][ar0] = pa0.x; As[nb][ac0 + 1][ar0] = pa0.y;
      As[nb][ac0 + 2][ar0] = pa0.z; As[nb][ac0 + 3][ar0] = pa0.w;
      As[nb][ac1 + 0][ar1] = pa1.x; As[nb][ac1 + 1][ar1] = pa1.y;
      As[nb][ac1 + 2][ar1] = pa1.z; As[nb][ac1 + 3][ar1] = pa1.w;
      *(float4*)&Bs[nb][br0][bc0] = pb0;
      *(float4*)&Bs[nb][br1][bc1] = pb1;
      __syncthreads();
      buf = nb;
    }
  }
#pragma unroll
  for (int i = 0; i < 8; i++) {
    size_t r = (size_t)(brow + ty * 8 + i) * N + bcol + tx * 8;
    *(float4*)&C[r]     = make_float4(acc[i][0], acc[i][1], acc[i][2], acc[i][3]);
    *(float4*)&C[r + 4] = make_float4(acc[i][4], acc[i][5], acc[i][6], acc[i][7]);
  }
}

// ---------------------------------------------------------------------------
// Flash attention with relative-position bias on scores and values.
// One block per (b, h, 64-row q tile). 256 threads, 4x4 microtiles.
// E buffer (128 rows) is time-shared: embk during S phase, embv during O.
// smem = 103 KB -> 2 blocks/SM. Softmax parallel across all 256 threads.
// ---------------------------------------------------------------------------
#define SMS 68
#define ATT_SMEM_FLOATS (4 * 64 * SMS + 128 * SMS + 3 * 64)
#define ATT_SMEM_BYTES  (ATT_SMEM_FLOATS * 4)

__global__ void __launch_bounds__(256, 2) attn_kernel(
    const float* __restrict__ qkv, const float* __restrict__ embk,
    const float* __restrict__ embv, float* __restrict__ y) {
  extern __shared__ float sm[];
  float* Qs  = sm;                  // 64 x 68
  float* Ks  = Qs + 64 * SMS;       // 64 x 68  (pre-scaled by 1/sqrt(d))
  float* Vs  = Ks + 64 * SMS;       // 64 x 68
  float* Ss  = Vs + 64 * SMS;       // 64 x 68  scores -> probs
  float* Es  = Ss + 64 * SMS;       // 128 x 68 staged embk, then embv
  float* m_s = Es + 128 * SMS;      // 64
  float* l_s = m_s + 64;            // 64
  float* cf  = l_s + 64;            // 64

  const int tid = threadIdx.x;
  const int tb = gridDim.x - 1 - blockIdx.x;   // heavy blocks first
  const int h = blockIdx.y, b = blockIdx.z;
  const int t0 = tb * 64;
  const int ty = tid >> 4, tx = tid & 15;
  const int tloc = ty * 4;   // micro-tile row base (t within block)
  const int cloc = tx * 4;   // micro-tile col base (s in S phase, e in O phase)

  // Load Q tile
#pragma unroll
  for (int i = 0; i < 16; i++) {
    int lin = i * 256 + tid;
    int t = lin >> 6, kk = lin & 63;
    Qs[t * SMS + kk] = qkv[(b * TSEQ + t0 + t) * (3 * CDIM) + h * 64 + kk];
  }
  if (tid < 64) { m_s[tid] = -1e30f; l_s[tid] = 0.f; }

  float accO[4][4];
#pragma unroll
  for (int i = 0; i < 4; i++)
#pragma unroll
    for (int j = 0; j < 4; j++) accO[i][j] = 0.f;

  for (int sb = 0; sb <= tb; sb++) {
    const int s0 = sb * 64;
    const int diff = t0 - s0;
    __syncthreads();   // prior O-phase reads of Vs/Es/Ss done

    // stage K (pre-scaled), V
#pragma unroll
    for (int i = 0; i < 16; i++) {
      int lin = i * 256 + tid;
      int s = lin >> 6, kk = lin & 63;
      int off = (b * TSEQ + s0 + s) * (3 * CDIM) + h * 64 + kk;
      Ks[s * SMS + kk] = qkv[off + CDIM] * 0.125f;  // 1/sqrt(64)
      Vs[s * SMS + kk] = qkv[off + 2 * CDIM];
    }
    // stage embk rows: row j holds embk[diff-63+j] (zero if out of range)
#pragma unroll
    for (int i = 0; i < 32; i++) {
      int lin = i * 256 + tid;
      int j = lin >> 6, kk = lin & 63;
      int rel = diff - 63 + j;
      bool ok = (rel >= 0) && (rel < TSEQ);
      Es[j * SMS + kk] = ok ? embk[rel * 64 + kk] : 0.f;
    }
    __syncthreads();

    // ---- S phase: S[t,s] = q . (k_scaled + embk[t-s]) ----
    float acc[4][4];
#pragma unroll
    for (int i = 0; i < 4; i++)
#pragma unroll
      for (int j = 0; j < 4; j++) acc[i][j] = 0.f;

    const int ebase = tloc - cloc + 63;   // only 7 distinct rel rows
#pragma unroll 4
    for (int kk = 0; kk < 64; kk += 4) {
      float4 qv[4], kv[4], ev[7];
#pragma unroll
      for (int i = 0; i < 4; i++) qv[i] = *(float4*)&Qs[(tloc + i) * SMS + kk];
#pragma unroll
      for (int j = 0; j < 4; j++) kv[j] = *(float4*)&Ks[(cloc + j) * SMS + kk];
#pragma unroll
      for (int m = 0; m < 7; m++) ev[m] = *(float4*)&Es[(ebase - 3 + m) * SMS + kk];
#pragma unroll
      for (int i = 0; i < 4; i++)
#pragma unroll
        for (int j = 0; j < 4; j++) {
          float4 q4 = qv[i], kb = kv[j], eb = ev[i - j + 3];
          acc[i][j] += q4.x * (kb.x + eb.x) + q4.y * (kb.y + eb.y)
                     + q4.z * (kb.z + eb.z) + q4.w * (kb.w + eb.w);
        }
    }
    // write scores with causal mask
#pragma unroll
    for (int i = 0; i < 4; i++)
#pragma unroll
      for (int j = 0; j < 4; j++) {
        bool masked = (sb == tb) && (cloc + j > tloc + i);
        Ss[(tloc + i) * SMS + cloc + j] = masked ? -1e30f : acc[i][j];
      }
    __syncthreads();

    // ---- online softmax: 4 lanes per row (row = tid>>2, quarter = tid&3) ----
    {
      const int r = tid >> 2, q = tid & 3;
      float* row = &Ss[r * SMS + q * 16];
      float4 v0 = *(float4*)&row[0],  v1 = *(float4*)&row[4];
      float4 v2 = *(float4*)&row[8],  v3 = *(float4*)&row[12];
      float mx = fmaxf(fmaxf(fmaxf(v0.x, v0.y), fmaxf(v0.z, v0.w)),
                       fmaxf(fmaxf(v1.x, v1.y), fmaxf(v1.z, v1.w)));
      mx = fmaxf(mx, fmaxf(fmaxf(fmaxf(v2.x, v2.y), fmaxf(v2.z, v2.w)),
                           fmaxf(fmaxf(v3.x, v3.y), fmaxf(v3.z, v3.w))));
      mx = fmaxf(mx, __shfl_xor_sync(0xffffffffu, mx, 1));
      mx = fmaxf(mx, __shfl_xor_sync(0xffffffffu, mx, 2));
      float mold = m_s[r];
      mx = fmaxf(mx, mold);
      v0.x = __expf(v0.x - mx); v0.y = __expf(v0.y - mx);
      v0.z = __expf(v0.z - mx); v0.w = __expf(v0.w - mx);
      v1.x = __expf(v1.x - mx); v1.y = __expf(v1.y - mx);
      v1.z = __expf(v1.z - mx); v1.w = __expf(v1.w - mx);
      v2.x = __expf(v2.x - mx); v2.y = __expf(v2.y - mx);
      v2.z = __expf(v2.z - mx); v2.w = __expf(v2.w - mx);
      v3.x = __expf(v3.x - mx); v3.y = __expf(v3.y - mx);
      v3.z = __expf(v3.z - mx); v3.w = __expf(v3.w - mx);
      *(float4*)&row[0] = v0;  *(float4*)&row[4] = v1;
      *(float4*)&row[8] = v2;  *(float4*)&row[12] = v3;
      float sum = v0.x + v0.y + v0.z + v0.w + v1.x + v1.y + v1.z + v1.w
                + v2.x + v2.y + v2.z + v2.w + v3.x + v3.y + v3.z + v3.w;
      sum += __shfl_xor_sync(0xffffffffu, sum, 1);
      sum += __shfl_xor_sync(0xffffffffu, sum, 2);
      if (q == 0) {
        float c = __expf(mold - mx);
        m_s[r] = mx;
        l_s[r] = l_s[r] * c + sum;
        cf[r] = c;
      }
    }
    // stage embv rows (Es reuse; S phase done with embk)
#pragma unroll
    for (int i = 0; i < 32; i++) {
      int lin = i * 256 + tid;
      int j = lin >> 6, kk = lin & 63;
      int rel = diff - 63 + j;
      bool ok = (rel >= 0) && (rel < TSEQ);
      Es[j * SMS + kk] = ok ? embv[rel * 64 + kk] : 0.f;
    }
    __syncthreads();

    // ---- O phase: O[t,e] += P[t,s] * (V[s,e] + embv[t-s][e]) ----
    float cfi[4];
#pragma unroll
    for (int i = 0; i < 4; i++) {
      cfi[i] = cf[tloc + i];
#pragma unroll
      for (int j = 0; j < 4; j++) accO[i][j] *= cfi[i];
    }
#pragma unroll 4
    for (int s = 0; s < 64; s++) {
      float4 v4 = *(float4*)&Vs[s * SMS + cloc];
      float p[4];
#pragma unroll
      for (int i = 0; i < 4; i++) p[i] = Ss[(tloc + i) * SMS + s];
#pragma unroll
      for (int i = 0; i < 4; i++) {
        float4 e4 = *(float4*)&Es[(tloc + i - s + 63) * SMS + cloc];
        accO[i][0] += p[i] * (v4.x + e4.x);
        accO[i][1] += p[i] * (v4.y + e4.y);
        accO[i][2] += p[i] * (v4.z + e4.z);
        accO[i][3] += p[i] * (v4.w + e4.w);
      }
    }
  }

  // epilogue: normalize and write y[b, t, h*64 + e]
#pragma unroll
  for (int i = 0; i < 4; i++) {
    float linv = 1.f / l_s[tloc + i];
    float4 o = make_float4(accO[i][0] * linv, accO[i][1] * linv,
                           accO[i][2] * linv, accO[i][3] * linv);
    *(float4*)&y[(b * TSEQ + t0 + tloc + i) * CDIM + h * 64 + cloc] = o;
  }
}

// ---------------------------------------------------------------------------
extern "C" void kernel_launch(void* const* d_in, const int* in_sizes, int n_in,
                              void* d_out, int out_size) {
  const float* x      = (const float*)d_in[0];
  const float* w_attn = (const float*)d_in[1];
  const float* w_proj = (const float*)d_in[2];
  const float* embk   = (const float*)d_in[3];
  const float* embv   = (const float*)d_in[4];
  float* out = (float*)d_out;

  float* qkv; cudaGetSymbolAddress((void**)&qkv, g_qkv);
  float* y;   cudaGetSymbolAddress((void**)&y, g_y);

  // QKV: [4096,1024] @ [1024,3072]
  sgemm_kernel<<<dim3(3072 / 128, 4096 / 128), 256>>>(x, w_attn, qkv,
                                                      BSZ * TSEQ, 3 * CDIM, CDIM);

  cudaFuncSetAttribute(attn_kernel, cudaFuncAttributeMaxDynamicSharedMemorySize,
                       ATT_SMEM_BYTES);
  attn_kernel<<<dim3(TSEQ / 64, NHEAD, BSZ), 256, ATT_SMEM_BYTES>>>(qkv, embk,
                                                                    embv, y);

  // Projection: [4096,1024] @ [1024,1024]
  sgemm_kernel<<<dim3(CDIM / 128, 4096 / 128), 256>>>(y, w_proj, out,
                                                      BSZ * TSEQ, CDIM, CDIM);
}

// round 5
// speedup vs baseline: 2.1511x; 2.1252x over previous
#include <cuda_runtime.h>
#include <math.h>

#define BSZ   4
#define TSEQ  1024
#define CDIM  1024
#define NHEAD 16
#define DHEAD 64

// Scratch (allocation-free: __device__ globals)
__device__ float g_qkv[BSZ * TSEQ * 3 * CDIM];   // [B,T,3C]
__device__ float g_y[BSZ * TSEQ * CDIM];         // [B,T,C] head-interleaved

// ---------------------------------------------------------------------------
// packed f32x2 helpers (FFMA2: 2 fp32 flops per instruction, PTX-only).
// Carrier type is u64 (PTX "l" constraint = 64-bit integer register).
// ---------------------------------------------------------------------------
typedef unsigned long long u64;

__device__ __forceinline__ u64 ffma2(u64 a, u64 b, u64 c) {
  u64 d; asm("fma.rn.f32x2 %0, %1, %2, %3;" : "=l"(d) : "l"(a), "l"(b), "l"(c));
  return d;
}
__device__ __forceinline__ u64 fadd2(u64 a, u64 b) {
  u64 d; asm("add.rn.f32x2 %0, %1, %2;" : "=l"(d) : "l"(a), "l"(b));
  return d;
}
__device__ __forceinline__ u64 fmul2(u64 a, u64 b) {
  u64 d; asm("mul.rn.f32x2 %0, %1, %2;" : "=l"(d) : "l"(a), "l"(b));
  return d;
}
__device__ __forceinline__ u64 fpack2(float lo, float hi) {
  u64 d; asm("mov.b64 %0, {%1, %2};" : "=l"(d) : "f"(lo), "f"(hi));
  return d;
}
__device__ __forceinline__ void funpack2(float& lo, float& hi, u64 d) {
  asm("mov.b64 {%0, %1}, %2;" : "=f"(lo), "=f"(hi) : "l"(d));
}

// ---------------------------------------------------------------------------
// fp32 SGEMM via FFMA2: C[M,N] = A[M,K] @ B[K,N], 128x128x16 tiles, 256 thr.
// Accumulators packed over column pairs; B pairs free from float4 loads.
// Per-thread cols: [tx*4, tx*4+4) and [64+tx*4, 64+tx*4+4)
// ---------------------------------------------------------------------------
__global__ void __launch_bounds__(256) sgemm_kernel(
    const float* __restrict__ A, const float* __restrict__ B,
    float* __restrict__ C, int M, int N, int K) {
  __shared__ float As[2][16][132];   // transposed A tile, padded
  __shared__ float Bs[2][16][132];

  const int tid  = threadIdx.x;
  const int brow = blockIdx.y * 128;
  const int bcol = blockIdx.x * 128;
  const int ty = tid >> 4, tx = tid & 15;

  const int ar0 = tid >> 2,          ac0 = (tid & 3) * 4;
  const int ar1 = (tid + 256) >> 2,  ac1 = ((tid + 256) & 3) * 4;
  const int br0 = tid >> 5,          bc0 = (tid & 31) * 4;
  const int br1 = (tid + 256) >> 5,  bc1 = ((tid + 256) & 31) * 4;

  u64 acc2[8][4];   // [row i][col-pair j2]
#pragma unroll
  for (int i = 0; i < 8; i++)
#pragma unroll
    for (int j = 0; j < 4; j++) acc2[i][j] = 0ull;

  // prologue: k-tile 0 -> buffer 0
  {
    float4 a0 = *(const float4*)&A[(size_t)(brow + ar0) * K + ac0];
    float4 a1 = *(const float4*)&A[(size_t)(brow + ar1) * K + ac1];
    As[0][ac0 + 0][ar0] = a0.x; As[0][ac0 + 1][ar0] = a0.y;
    As[0][ac0 + 2][ar0] = a0.z; As[0][ac0 + 3][ar0] = a0.w;
    As[0][ac1 + 0][ar1] = a1.x; As[0][ac1 + 1][ar1] = a1.y;
    As[0][ac1 + 2][ar1] = a1.z; As[0][ac1 + 3][ar1] = a1.w;
    *(float4*)&Bs[0][br0][bc0] = *(const float4*)&B[(size_t)br0 * N + bcol + bc0];
    *(float4*)&Bs[0][br1][bc1] = *(const float4*)&B[(size_t)br1 * N + bcol + bc1];
  }
  __syncthreads();

  int buf = 0;
  for (int k0 = 0; k0 < K; k0 += 16) {
    const bool has_next = (k0 + 16) < K;
    float4 pa0, pa1, pb0, pb1;
    if (has_next) {
      pa0 = *(const float4*)&A[(size_t)(brow + ar0) * K + k0 + 16 + ac0];
      pa1 = *(const float4*)&A[(size_t)(brow + ar1) * K + k0 + 16 + ac1];
      pb0 = *(const float4*)&B[(size_t)(k0 + 16 + br0) * N + bcol + bc0];
      pb1 = *(const float4*)&B[(size_t)(k0 + 16 + br1) * N + bcol + bc1];
    }
#pragma unroll
    for (int kk = 0; kk < 16; kk++) {
      float a[8];
      *(float4*)&a[0] = *(float4*)&As[buf][kk][ty * 8];
      *(float4*)&a[4] = *(float4*)&As[buf][kk][ty * 8 + 4];
      u64 b2[4];
      *(ulonglong2*)&b2[0] = *(ulonglong2*)&Bs[buf][kk][tx * 4];       // cols tx*4..+3
      *(ulonglong2*)&b2[2] = *(ulonglong2*)&Bs[buf][kk][64 + tx * 4];  // cols 64+tx*4..+3
      u64 ad[8];
#pragma unroll
      for (int i = 0; i < 8; i++) ad[i] = fpack2(a[i], a[i]);
#pragma unroll
      for (int i = 0; i < 8; i++)
#pragma unroll
        for (int j = 0; j < 4; j++) acc2[i][j] = ffma2(ad[i], b2[j], acc2[i][j]);
    }
    if (has_next) {
      int nb = buf ^ 1;
      As[nb][ac0 + 0][ar0] = pa0.x; As[nb][ac0 + 1][ar0] = pa0.y;
      As[nb][ac0 + 2][ar0] = pa0.z; As[nb][ac0 + 3][ar0] = pa0.w;
      As[nb][ac1 + 0][ar1] = pa1.x; As[nb][ac1 + 1][ar1] = pa1.y;
      As[nb][ac1 + 2][ar1] = pa1.z; As[nb][ac1 + 3][ar1] = pa1.w;
      *(float4*)&Bs[nb][br0][bc0] = pb0;
      *(float4*)&Bs[nb][br1][bc1] = pb1;
      __syncthreads();
      buf = nb;
    }
  }
#pragma unroll
  for (int i = 0; i < 8; i++) {
    size_t r = (size_t)(brow + ty * 8 + i) * N + bcol;
    *(ulonglong2*)&C[r + tx * 4]      = make_ulonglong2(acc2[i][0], acc2[i][1]);
    *(ulonglong2*)&C[r + 64 + tx * 4] = make_ulonglong2(acc2[i][2], acc2[i][3]);
  }
}

// ---------------------------------------------------------------------------
// Flash attention with RPE on scores and values.
// Q/K/V/E tiles: stride-64 rows with XOR chunk swizzle (conflict-free for the
// stride-4-row access pattern of the S phase). Ss: stride 68 (already optimal).
// Inner math packed f32x2. E buffer time-shared (embk for S, embv for O).
// ---------------------------------------------------------------------------
__device__ __forceinline__ int swz(int r, int kk) {
  return r * 64 + ((((kk >> 2) ^ (r >> 2)) & 15) << 2) + (kk & 3);
}

#define SSTR 68
#define ATT_SMEM_FLOATS (3 * 64 * 64 + 128 * 64 + 64 * SSTR + 3 * 64)
#define ATT_SMEM_BYTES  (ATT_SMEM_FLOATS * 4)

__global__ void __launch_bounds__(256, 2) attn_kernel(
    const float* __restrict__ qkv, const float* __restrict__ embk,
    const float* __restrict__ embv, float* __restrict__ y) {
  extern __shared__ float sm[];
  float* Qs  = sm;                  // 64 x 64 swizzled
  float* Ks  = Qs + 64 * 64;        // 64 x 64 swizzled (pre-scaled)
  float* Vs  = Ks + 64 * 64;        // 64 x 64 swizzled
  float* Es  = Vs + 64 * 64;        // 128 x 64 swizzled (embk then embv)
  float* Ss  = Es + 128 * 64;       // 64 x 68 plain
  float* m_s = Ss + 64 * SSTR;      // 64
  float* l_s = m_s + 64;            // 64
  float* cf  = l_s + 64;            // 64

  const int tid = threadIdx.x;
  const int tb = gridDim.x - 1 - blockIdx.x;   // heavy blocks first
  const int h = blockIdx.y, b = blockIdx.z;
  const int t0 = tb * 64;
  const int ty = tid >> 4, tx = tid & 15;
  const int tloc = ty * 4;
  const int cloc = tx * 4;

  // Load Q tile
#pragma unroll
  for (int i = 0; i < 16; i++) {
    int lin = i * 256 + tid;
    int t = lin >> 6, kk = lin & 63;
    Qs[swz(t, kk)] = qkv[(b * TSEQ + t0 + t) * (3 * CDIM) + h * 64 + kk];
  }
  if (tid < 64) { m_s[tid] = -1e30f; l_s[tid] = 0.f; }

  u64 accO2[4][2];   // [row i][e-pair]
#pragma unroll
  for (int i = 0; i < 4; i++) { accO2[i][0] = 0ull; accO2[i][1] = 0ull; }

  for (int sb = 0; sb <= tb; sb++) {
    const int s0 = sb * 64;
    const int diff = t0 - s0;
    __syncthreads();   // prior O-phase reads done

    // stage K (pre-scaled), V
#pragma unroll
    for (int i = 0; i < 16; i++) {
      int lin = i * 256 + tid;
      int s = lin >> 6, kk = lin & 63;
      int off = (b * TSEQ + s0 + s) * (3 * CDIM) + h * 64 + kk;
      Ks[swz(s, kk)] = qkv[off + CDIM] * 0.125f;
      Vs[swz(s, kk)] = qkv[off + 2 * CDIM];
    }
    // stage embk rows: row j holds embk[diff-63+j] (zero out of range)
#pragma unroll
    for (int i = 0; i < 32; i++) {
      int lin = i * 256 + tid;
      int j = lin >> 6, kk = lin & 63;
      int rel = diff - 63 + j;
      bool ok = (rel >= 0) && (rel < TSEQ);
      Es[swz(j, kk)] = ok ? embk[rel * 64 + kk] : 0.f;
    }
    __syncthreads();

    // ---- S phase: S[t,s] = q . (k_scaled + embk[t-s]), packed over kk pairs
    u64 acc2[4][4];
#pragma unroll
    for (int i = 0; i < 4; i++)
#pragma unroll
      for (int j = 0; j < 4; j++) acc2[i][j] = 0ull;

    const int ebase = tloc - cloc + 60;   // 7 distinct rel rows: ebase..ebase+6
#pragma unroll 4
    for (int kk = 0; kk < 64; kk += 4) {
      ulonglong2 qd[4], kd[4], ed[7];
#pragma unroll
      for (int i = 0; i < 4; i++) qd[i] = *(ulonglong2*)&Qs[swz(tloc + i, kk)];
#pragma unroll
      for (int j = 0; j < 4; j++) kd[j] = *(ulonglong2*)&Ks[swz(cloc + j, kk)];
#pragma unroll
      for (int m = 0; m < 7; m++) ed[m] = *(ulonglong2*)&Es[swz(ebase + m, kk)];
#pragma unroll
      for (int i = 0; i < 4; i++)
#pragma unroll
        for (int j = 0; j < 4; j++) {
          ulonglong2 e2 = ed[i - j + 3];
          acc2[i][j] = ffma2(qd[i].x, fadd2(kd[j].x, e2.x), acc2[i][j]);
          acc2[i][j] = ffma2(qd[i].y, fadd2(kd[j].y, e2.y), acc2[i][j]);
        }
    }
    // reduce pairs, causal mask, vector-store scores
#pragma unroll
    for (int i = 0; i < 4; i++) {
      float sv[4];
#pragma unroll
      for (int j = 0; j < 4; j++) {
        float lo, hi; funpack2(lo, hi, acc2[i][j]);
        bool masked = (sb == tb) && (cloc + j > tloc + i);
        sv[j] = masked ? -1e30f : (lo + hi);
      }
      *(float4*)&Ss[(tloc + i) * SSTR + cloc] = *(float4*)sv;
    }
    __syncthreads();

    // ---- online softmax: 4 lanes per row ----
    {
      const int r = tid >> 2, q = tid & 3;
      float* row = &Ss[r * SSTR + q * 16];
      float4 v0 = *(float4*)&row[0],  v1 = *(float4*)&row[4];
      float4 v2 = *(float4*)&row[8],  v3 = *(float4*)&row[12];
      float mx = fmaxf(fmaxf(fmaxf(v0.x, v0.y), fmaxf(v0.z, v0.w)),
                       fmaxf(fmaxf(v1.x, v1.y), fmaxf(v1.z, v1.w)));
      mx = fmaxf(mx, fmaxf(fmaxf(fmaxf(v2.x, v2.y), fmaxf(v2.z, v2.w)),
                           fmaxf(fmaxf(v3.x, v3.y), fmaxf(v3.z, v3.w))));
      mx = fmaxf(mx, __shfl_xor_sync(0xffffffffu, mx, 1));
      mx = fmaxf(mx, __shfl_xor_sync(0xffffffffu, mx, 2));
      float mold = m_s[r];
      mx = fmaxf(mx, mold);
      v0.x = __expf(v0.x - mx); v0.y = __expf(v0.y - mx);
      v0.z = __expf(v0.z - mx); v0.w = __expf(v0.w - mx);
      v1.x = __expf(v1.x - mx); v1.y = __expf(v1.y - mx);
      v1.z = __expf(v1.z - mx); v1.w = __expf(v1.w - mx);
      v2.x = __expf(v2.x - mx); v2.y = __expf(v2.y - mx);
      v2.z = __expf(v2.z - mx); v2.w = __expf(v2.w - mx);
      v3.x = __expf(v3.x - mx); v3.y = __expf(v3.y - mx);
      v3.z = __expf(v3.z - mx); v3.w = __expf(v3.w - mx);
      *(float4*)&row[0] = v0;  *(float4*)&row[4] = v1;
      *(float4*)&row[8] = v2;  *(float4*)&row[12] = v3;
      float sum = v0.x + v0.y + v0.z + v0.w + v1.x + v1.y + v1.z + v1.w
                + v2.x + v2.y + v2.z + v2.w + v3.x + v3.y + v3.z + v3.w;
      sum += __shfl_xor_sync(0xffffffffu, sum, 1);
      sum += __shfl_xor_sync(0xffffffffu, sum, 2);
      if (q == 0) {
        float c = __expf(mold - mx);
        m_s[r] = mx;
        l_s[r] = l_s[r] * c + sum;
        cf[r] = c;
      }
    }
    // stage embv rows (Es reuse)
#pragma unroll
    for (int i = 0; i < 32; i++) {
      int lin = i * 256 + tid;
      int j = lin >> 6, kk = lin & 63;
      int rel = diff - 63 + j;
      bool ok = (rel >= 0) && (rel < TSEQ);
      Es[swz(j, kk)] = ok ? embv[rel * 64 + kk] : 0.f;
    }
    __syncthreads();

    // ---- O phase: O[t,e] += P[t,s] * (V[s,e] + embv[t-s][e]), packed over e
#pragma unroll
    for (int i = 0; i < 4; i++) {
      u64 cd = fpack2(cf[tloc + i], cf[tloc + i]);
      accO2[i][0] = fmul2(accO2[i][0], cd);
      accO2[i][1] = fmul2(accO2[i][1], cd);
    }
#pragma unroll 4
    for (int s = 0; s < 64; s++) {
      ulonglong2 vd = *(ulonglong2*)&Vs[swz(s, cloc)];
      float p[4];
#pragma unroll
      for (int i = 0; i < 4; i++) p[i] = Ss[(tloc + i) * SSTR + s];
#pragma unroll
      for (int i = 0; i < 4; i++) {
        ulonglong2 evd = *(ulonglong2*)&Es[swz(tloc + i - s + 63, cloc)];
        u64 pd = fpack2(p[i], p[i]);
        accO2[i][0] = ffma2(pd, fadd2(vd.x, evd.x), accO2[i][0]);
        accO2[i][1] = ffma2(pd, fadd2(vd.y, evd.y), accO2[i][1]);
      }
    }
  }

  // epilogue: normalize and write y[b, t, h*64 + e]
#pragma unroll
  for (int i = 0; i < 4; i++) {
    float linv = 1.f / l_s[tloc + i];
    float o[4];
    funpack2(o[0], o[1], accO2[i][0]);
    funpack2(o[2], o[3], accO2[i][1]);
    float4 ov = make_float4(o[0] * linv, o[1] * linv, o[2] * linv, o[3] * linv);
    *(float4*)&y[(b * TSEQ + t0 + tloc + i) * CDIM + h * 64 + cloc] = ov;
  }
}

// ---------------------------------------------------------------------------
extern "C" void kernel_launch(void* const* d_in, const int* in_sizes, int n_in,
                              void* d_out, int out_size) {
  const float* x      = (const float*)d_in[0];
  const float* w_attn = (const float*)d_in[1];
  const float* w_proj = (const float*)d_in[2];
  const float* embk   = (const float*)d_in[3];
  const float* embv   = (const float*)d_in[4];
  float* out = (float*)d_out;

  float* qkv; cudaGetSymbolAddress((void**)&qkv, g_qkv);
  float* y;   cudaGetSymbolAddress((void**)&y, g_y);

  // QKV: [4096,1024] @ [1024,3072]
  sgemm_kernel<<<dim3(3072 / 128, 4096 / 128), 256>>>(x, w_attn, qkv,
                                                      BSZ * TSEQ, 3 * CDIM, CDIM);

  cudaFuncSetAttribute(attn_kernel, cudaFuncAttributeMaxDynamicSharedMemorySize,
                       ATT_SMEM_BYTES);
  attn_kernel<<<dim3(TSEQ / 64, NHEAD, BSZ), 256, ATT_SMEM_BYTES>>>(qkv, embk,
                                                                    embv, y);

  // Projection: [4096,1024] @ [1024,1024]
  sgemm_kernel<<<dim3(CDIM / 128, 4096 / 128), 256>>>(y, w_proj, out,
                                                      BSZ * TSEQ, CDIM, CDIM);
}

// round 7
// speedup vs baseline: 3.7167x; 1.7278x over previous
#include <cuda_runtime.h>
#include <cuda_bf16.h>
#include <math.h>

#define BSZ   4
#define TSEQ  1024
#define CDIM  1024
#define NHEAD 16
#define DHEAD 64

typedef unsigned long long u64;

#if defined(__CUDA_ARCH_FEAT_SM103_ALL) || \
    (defined(__CUDA_ARCH_SPECIFIC__) && (__CUDA_ARCH_SPECIFIC__ == 1030))
#define HAS_TCGEN05 1
#else
#define HAS_TCGEN05 0
#endif

// ---------------- scratch (allocation-free: __device__ globals) -------------
__device__ float g_qkv[BSZ * TSEQ * 3 * CDIM];   // [B,T,3C] fp32
__device__ float g_y[BSZ * TSEQ * CDIM];         // [B,T,C] fp32
__device__ __nv_bfloat16 g_xh[BSZ * TSEQ * CDIM], g_xl[BSZ * TSEQ * CDIM];
__device__ __nv_bfloat16 g_wah[3 * CDIM * CDIM], g_wal[3 * CDIM * CDIM]; // [N,K]
__device__ __nv_bfloat16 g_wph[CDIM * CDIM],     g_wpl[CDIM * CDIM];     // [N,K]
__device__ __nv_bfloat16 g_yh[BSZ * TSEQ * CDIM], g_yl[BSZ * TSEQ * CDIM];

// ---------------- packed f32x2 helpers --------------------------------------
__device__ __forceinline__ u64 ffma2(u64 a, u64 b, u64 c) {
  u64 d; asm("fma.rn.f32x2 %0, %1, %2, %3;" : "=l"(d) : "l"(a), "l"(b), "l"(c));
  return d;
}
__device__ __forceinline__ u64 fadd2(u64 a, u64 b) {
  u64 d; asm("add.rn.f32x2 %0, %1, %2;" : "=l"(d) : "l"(a), "l"(b));
  return d;
}
__device__ __forceinline__ u64 fmul2(u64 a, u64 b) {
  u64 d; asm("mul.rn.f32x2 %0, %1, %2;" : "=l"(d) : "l"(a), "l"(b));
  return d;
}
__device__ __forceinline__ u64 fpack2(float lo, float hi) {
  u64 d; asm("mov.b64 %0, {%1, %2};" : "=l"(d) : "f"(lo), "f"(hi));
  return d;
}
__device__ __forceinline__ void funpack2(float& lo, float& hi, u64 d) {
  asm("mov.b64 {%0, %1}, %2;" : "=f"(lo), "=f"(hi) : "l"(d));
}

// ---------------- generic plumbing (legal on all targets) -------------------
__device__ __forceinline__ unsigned smem_u32(const void* p) {
  unsigned a;
  asm("{ .reg .u64 t; cvta.to.shared.u64 t, %1; cvt.u32.u64 %0, t; }"
      : "=r"(a) : "l"(p));
  return a;
}
__device__ __forceinline__ unsigned elect_one() {
  unsigned p;
  asm volatile("{ .reg .pred P; elect.sync _|P, 0xFFFFFFFF; selp.b32 %0,1,0,P; }"
               : "=r"(p));
  return p;
}
__device__ __forceinline__ void cp_async16(unsigned dst, const void* src) {
  asm volatile("cp.async.cg.shared.global [%0], [%1], 16;"
               :: "r"(dst), "l"(src) : "memory");
}
#define CP_COMMIT() asm volatile("cp.async.commit_group;" ::: "memory")
#define CP_WAIT(n)  asm volatile("cp.async.wait_group %0;" :: "n"(n) : "memory")

__device__ __forceinline__ void mbar_init(unsigned a, unsigned cnt) {
  asm volatile("mbarrier.init.shared.b64 [%0], %1;" :: "r"(a), "r"(cnt) : "memory");
}
__device__ __forceinline__ void mbar_wait(unsigned a, unsigned phase) {
  asm volatile(
      "{\n\t.reg .pred P;\n\t"
      "W_%=:\n\t"
      "mbarrier.try_wait.parity.acquire.cta.shared::cta.b64 P, [%0], %1, 0x989680;\n\t"
      "@!P bra W_%=;\n\t}"
      :: "r"(a), "r"(phase) : "memory");
}

#define SWZ128(o) ((o) ^ (((o) >> 3) & 0x70))
__device__ __forceinline__ u64 make_desc(unsigned addr) {
  const u64 base = (2ull << 61) | (1ull << 46) | (64ull << 32) | (1ull << 16);
  return base | ((u64)(addr >> 4) & 0x3FFF);
}
// idesc: c=F32, a=BF16, b=BF16, M=128, N=128
#define GEMM_IDESC ((1u<<4)|(1u<<7)|(1u<<10)|((128u/8)<<17)|((128u/16)<<24))

// ---------------- tcgen05 wrappers (only compiled on sm_103a pass) ----------
#if HAS_TCGEN05
__device__ __forceinline__ void tmem_alloc(unsigned smem_dst, unsigned ncols) {
  asm volatile("tcgen05.alloc.cta_group::1.sync.aligned.shared::cta.b32 [%0], %1;"
               :: "r"(smem_dst), "r"(ncols) : "memory");
}
__device__ __forceinline__ void tmem_dealloc(unsigned tmem, unsigned ncols) {
  asm volatile("tcgen05.dealloc.cta_group::1.sync.aligned.b32 %0, %1;"
               :: "r"(tmem), "r"(ncols));
}
__device__ __forceinline__ void tmem_relinquish() {
  asm volatile("tcgen05.relinquish_alloc_permit.cta_group::1.sync.aligned;");
}
__device__ __forceinline__ void tc_commit(unsigned mbar) {
  asm volatile(
      "tcgen05.commit.cta_group::1.mbarrier::arrive::one.shared::cluster.b64 [%0];"
      :: "r"(mbar) : "memory");
}
#define TC_FENCE_AFTER()  asm volatile("tcgen05.fence::after_thread_sync;" ::: "memory")
#define TC_WAIT_LD()      asm volatile("tcgen05.wait::ld.sync.aligned;" ::: "memory")

__device__ __forceinline__ void mma_f16_ss(unsigned d_tmem, u64 a_desc, u64 b_desc,
                                           unsigned idesc, unsigned enable) {
  asm volatile(
      "{\n\t.reg .pred p;\n\tsetp.ne.u32 p, %4, 0;\n\t"
      "tcgen05.mma.cta_group::1.kind::f16 [%0], %1, %2, %3, {%5,%5,%5,%5}, p;\n\t}"
      :: "r"(d_tmem), "l"(a_desc), "l"(b_desc), "r"(idesc), "r"(enable), "r"(0u)
      : "memory");
}
__device__ __forceinline__ void tmem_ld32(unsigned* r, unsigned addr) {
  asm volatile(
      "tcgen05.ld.sync.aligned.32x32b.x32.b32 "
      "{%0,%1,%2,%3,%4,%5,%6,%7,%8,%9,%10,%11,%12,%13,%14,%15,"
      "%16,%17,%18,%19,%20,%21,%22,%23,%24,%25,%26,%27,%28,%29,%30,%31}, [%32];"
      : "=r"(r[0]),"=r"(r[1]),"=r"(r[2]),"=r"(r[3]),"=r"(r[4]),"=r"(r[5]),
        "=r"(r[6]),"=r"(r[7]),"=r"(r[8]),"=r"(r[9]),"=r"(r[10]),"=r"(r[11]),
        "=r"(r[12]),"=r"(r[13]),"=r"(r[14]),"=r"(r[15]),"=r"(r[16]),"=r"(r[17]),
        "=r"(r[18]),"=r"(r[19]),"=r"(r[20]),"=r"(r[21]),"=r"(r[22]),"=r"(r[23]),
        "=r"(r[24]),"=r"(r[25]),"=r"(r[26]),"=r"(r[27]),"=r"(r[28]),"=r"(r[29]),
        "=r"(r[30]),"=r"(r[31])
      : "r"(addr));
}
#endif  // HAS_TCGEN05

// ---------------------------------------------------------------------------
// Unified GEMM. On sm_103a: bf16x3 tcgen05 (C = Ah*Bh + Al*Bh + Ah*Bl),
// A*:[M,K] bf16 K-major, B*:[N,K] bf16 K-major, 128x128 tile, K chunks of 64,
// double-buffered cp.async. Otherwise: fp32 FFMA2 SGEMM on Af [M,K] and
// Bf [K,N] (the original operands). Same launch config either way.
// ---------------------------------------------------------------------------
#define G_TILE  (128 * 64 * 2)     // 16KB per bf16 tile
#define G_BUF   (4 * G_TILE)       // Ah,Al,Bh,Bl
#define G_SMEM  (1024 + 2 * G_BUF) // ~129KB

__global__ void __launch_bounds__(256) gemm_kernel(
    const __nv_bfloat16* __restrict__ Ah, const __nv_bfloat16* __restrict__ Al,
    const __nv_bfloat16* __restrict__ Bh, const __nv_bfloat16* __restrict__ Bl,
    const float* __restrict__ Af, const float* __restrict__ Bf,
    float* __restrict__ C, int M, int N, int K) {
  extern __shared__ char smem[];
  const int tid = threadIdx.x;
  const int brow = blockIdx.y * 128, bcol = blockIdx.x * 128;

#if HAS_TCGEN05
  const unsigned sb = smem_u32(smem);
  const int wid = tid >> 5, lid = tid & 31;
  const int NKT = K >> 6;
  const unsigned mb0 = sb + 16, mb1 = sb + 24;
  const unsigned tiles = sb + 1024;

  if (tid == 0) { mbar_init(mb0, 1); mbar_init(mb1, 1); }
  if (wid == 0) { tmem_alloc(sb, 128); tmem_relinquish(); }
  __syncthreads();
  unsigned tmem;
  asm volatile("ld.shared.b32 %0, [%1];" : "=r"(tmem) : "r"(sb));

  const __nv_bfloat16* srcs[4] = {Ah, Al, Bh, Bl};
  const int rb[4] = {brow, brow, bcol, bcol};

  auto stage = [&](int buf, int kt) {
#pragma unroll
    for (int t = 0; t < 4; t++) {
      const __nv_bfloat16* s = srcs[t] + (size_t)rb[t] * K + kt * 64;
      unsigned tb = tiles + buf * G_BUF + t * G_TILE;
#pragma unroll
      for (int it = 0; it < 4; it++) {
        int i = it * 256 + tid;          // 0..1023
        int r = i >> 3, c = i & 7;
        cp_async16(tb + SWZ128(r * 128 + c * 16), s + (size_t)r * K + c * 8);
      }
    }
  };

  stage(0, 0);
  CP_COMMIT();
  int ph0 = 0, ph1 = 0;

  for (int kt = 0; kt < NKT; kt++) {
    const int buf = kt & 1;
    if (kt > 0) {
      if (((kt - 1) & 1) == 0) { mbar_wait(mb0, ph0 & 1); ph0++; }
      else                     { mbar_wait(mb1, ph1 & 1); ph1++; }
    }
    if (kt + 1 < NKT) { stage(buf ^ 1, kt + 1); CP_COMMIT(); CP_WAIT(1); }
    else              { CP_WAIT(0); }
    __syncthreads();

    if (wid == 0 && elect_one()) {
      asm volatile("fence.proxy.async.shared::cta;" ::: "memory");
      unsigned base = tiles + buf * G_BUF;
      u64 dAh = make_desc(base),              dAl = make_desc(base + G_TILE);
      u64 dBh = make_desc(base + 2 * G_TILE), dBl = make_desc(base + 3 * G_TILE);
      u64 da[3] = {dAh, dAl, dAh};
      u64 db[3] = {dBh, dBh, dBl};
#pragma unroll
      for (int p = 0; p < 3; p++)
#pragma unroll
        for (int ks = 0; ks < 4; ks++)
          mma_f16_ss(tmem, da[p] + ks * 2, db[p] + ks * 2, GEMM_IDESC,
                     !(kt == 0 && p == 0 && ks == 0));
      tc_commit(buf == 0 ? mb0 : mb1);
    }
  }
  if (((NKT - 1) & 1) == 0) { mbar_wait(mb0, ph0 & 1); }
  else                      { mbar_wait(mb1, ph1 & 1); }
  TC_FENCE_AFTER();

  if (wid < 4) {
    const size_t row = (size_t)brow + wid * 32 + lid;
#pragma unroll
    for (int cb = 0; cb < 128; cb += 32) {
      unsigned r[32];
      tmem_ld32(r, tmem + cb);
      TC_WAIT_LD();
      float* dst = &C[row * N + bcol + cb];
#pragma unroll
      for (int c = 0; c < 32; c += 4)
        *(float4*)&dst[c] = make_float4(__uint_as_float(r[c]), __uint_as_float(r[c+1]),
                                        __uint_as_float(r[c+2]), __uint_as_float(r[c+3]));
    }
  }
  __syncthreads();
  if (wid == 0) tmem_dealloc(tmem, 128);

#else  // ---------------- fallback: fp32 FFMA2 SGEMM (R5 design) ------------
  float (*As)[16][132] = reinterpret_cast<float(*)[16][132]>(smem);
  float (*Bs)[16][132] = reinterpret_cast<float(*)[16][132]>(smem + 2 * 16 * 132 * 4);
  const int ty = tid >> 4, tx = tid & 15;
  const int ar0 = tid >> 2,          ac0 = (tid & 3) * 4;
  const int ar1 = (tid + 256) >> 2,  ac1 = ((tid + 256) & 3) * 4;
  const int br0 = tid >> 5,          bc0 = (tid & 31) * 4;
  const int br1 = (tid + 256) >> 5,  bc1 = ((tid + 256) & 31) * 4;

  u64 acc2[8][4];
#pragma unroll
  for (int i = 0; i < 8; i++)
#pragma unroll
    for (int j = 0; j < 4; j++) acc2[i][j] = 0ull;

  {
    float4 a0 = *(const float4*)&Af[(size_t)(brow + ar0) * K + ac0];
    float4 a1 = *(const float4*)&Af[(size_t)(brow + ar1) * K + ac1];
    As[0][ac0 + 0][ar0] = a0.x; As[0][ac0 + 1][ar0] = a0.y;
    As[0][ac0 + 2][ar0] = a0.z; As[0][ac0 + 3][ar0] = a0.w;
    As[0][ac1 + 0][ar1] = a1.x; As[0][ac1 + 1][ar1] = a1.y;
    As[0][ac1 + 2][ar1] = a1.z; As[0][ac1 + 3][ar1] = a1.w;
    *(float4*)&Bs[0][br0][bc0] = *(const float4*)&Bf[(size_t)br0 * N + bcol + bc0];
    *(float4*)&Bs[0][br1][bc1] = *(const float4*)&Bf[(size_t)br1 * N + bcol + bc1];
  }
  __syncthreads();

  int buf = 0;
  for (int k0 = 0; k0 < K; k0 += 16) {
    const bool has_next = (k0 + 16) < K;
    float4 pa0, pa1, pb0, pb1;
    if (has_next) {
      pa0 = *(const float4*)&Af[(size_t)(brow + ar0) * K + k0 + 16 + ac0];
      pa1 = *(const float4*)&Af[(size_t)(brow + ar1) * K + k0 + 16 + ac1];
      pb0 = *(const float4*)&Bf[(size_t)(k0 + 16 + br0) * N + bcol + bc0];
      pb1 = *(const float4*)&Bf[(size_t)(k0 + 16 + br1) * N + bcol + bc1];
    }
#pragma unroll
    for (int kk = 0; kk < 16; kk++) {
      float a[8];
      *(float4*)&a[0] = *(float4*)&As[buf][kk][ty * 8];
      *(float4*)&a[4] = *(float4*)&As[buf][kk][ty * 8 + 4];
      u64 b2[4];
      *(ulonglong2*)&b2[0] = *(ulonglong2*)&Bs[buf][kk][tx * 4];
      *(ulonglong2*)&b2[2] = *(ulonglong2*)&Bs[buf][kk][64 + tx * 4];
      u64 ad[8];
#pragma unroll
      for (int i = 0; i < 8; i++) ad[i] = fpack2(a[i], a[i]);
#pragma unroll
      for (int i = 0; i < 8; i++)
#pragma unroll
        for (int j = 0; j < 4; j++) acc2[i][j] = ffma2(ad[i], b2[j], acc2[i][j]);
    }
    if (has_next) {
      int nb = buf ^ 1;
      As[nb][ac0 + 0][ar0] = pa0.x; As[nb][ac0 + 1][ar0] = pa0.y;
      As[nb][ac0 + 2][ar0] = pa0.z; As[nb][ac0 + 3][ar0] = pa0.w;
      As[nb][ac1 + 0][ar1] = pa1.x; As[nb][ac1 + 1][ar1] = pa1.y;
      As[nb][ac1 + 2][ar1] = pa1.z; As[nb][ac1 + 3][ar1] = pa1.w;
      *(float4*)&Bs[nb][br0][bc0] = pb0;
      *(float4*)&Bs[nb][br1][bc1] = pb1;
      __syncthreads();
      buf = nb;
    }
  }
#pragma unroll
  for (int i = 0; i < 8; i++) {
    size_t r = (size_t)(brow + ty * 8 + i) * N + bcol;
    *(ulonglong2*)&C[r + tx * 4]      = make_ulonglong2(acc2[i][0], acc2[i][1]);
    *(ulonglong2*)&C[r + 64 + tx * 4] = make_ulonglong2(acc2[i][2], acc2[i][3]);
  }
#endif
}

// ---------------------------------------------------------------------------
// split fp32 -> (hi, lo) bf16, elementwise (vectorized by 4)
// ---------------------------------------------------------------------------
__global__ void __launch_bounds__(256) split_kernel(
    const float* __restrict__ src, __nv_bfloat16* __restrict__ h,
    __nv_bfloat16* __restrict__ l, int n4) {
  int i = blockIdx.x * 256 + threadIdx.x;
  if (i >= n4) return;
  float4 v = ((const float4*)src)[i];
  __nv_bfloat16 h0 = __float2bfloat16_rn(v.x), h1 = __float2bfloat16_rn(v.y);
  __nv_bfloat16 h2 = __float2bfloat16_rn(v.z), h3 = __float2bfloat16_rn(v.w);
  __nv_bfloat16 l0 = __float2bfloat16_rn(v.x - __bfloat162float(h0));
  __nv_bfloat16 l1 = __float2bfloat16_rn(v.y - __bfloat162float(h1));
  __nv_bfloat16 l2 = __float2bfloat16_rn(v.z - __bfloat162float(h2));
  __nv_bfloat16 l3 = __float2bfloat16_rn(v.w - __bfloat162float(h3));
  ((__nv_bfloat162*)h)[i * 2]     = __nv_bfloat162(h0, h1);
  ((__nv_bfloat162*)h)[i * 2 + 1] = __nv_bfloat162(h2, h3);
  ((__nv_bfloat162*)l)[i * 2]     = __nv_bfloat162(l0, l1);
  ((__nv_bfloat162*)l)[i * 2 + 1] = __nv_bfloat162(l2, l3);
}

// split + transpose: w[K,N] fp32 -> h,l[N,K] bf16 (tiled 32x32)
__global__ void __launch_bounds__(256) splitT_kernel(
    const float* __restrict__ w, __nv_bfloat16* __restrict__ h,
    __nv_bfloat16* __restrict__ l, int K, int N) {
  __shared__ float t[32][33];
  int n0 = blockIdx.x * 32, k0 = blockIdx.y * 32;
  int tx = threadIdx.x, ty = threadIdx.y;   // 32 x 8
#pragma unroll
  for (int i = 0; i < 32; i += 8)
    t[ty + i][tx] = w[(size_t)(k0 + ty + i) * N + n0 + tx];
  __syncthreads();
#pragma unroll
  for (int i = 0; i < 32; i += 8) {
    float v = t[tx][ty + i];
    __nv_bfloat16 hh = __float2bfloat16_rn(v);
    __nv_bfloat16 ll = __float2bfloat16_rn(v - __bfloat162float(hh));
    size_t o = (size_t)(n0 + ty + i) * K + k0 + tx;
    h[o] = hh; l[o] = ll;
  }
}

// ---------------------------------------------------------------------------
// Flash attention with RPE (unchanged from R5 passing version)
// ---------------------------------------------------------------------------
__device__ __forceinline__ int swz(int r, int kk) {
  return r * 64 + ((((kk >> 2) ^ (r >> 2)) & 15) << 2) + (kk & 3);
}

#define SSTR 68
#define ATT_SMEM_FLOATS (3 * 64 * 64 + 128 * 64 + 64 * SSTR + 3 * 64)
#define ATT_SMEM_BYTES  (ATT_SMEM_FLOATS * 4)

__global__ void __launch_bounds__(256, 2) attn_kernel(
    const float* __restrict__ qkv, const float* __restrict__ embk,
    const float* __restrict__ embv, float* __restrict__ y) {
  extern __shared__ float sm[];
  float* Qs  = sm;
  float* Ks  = Qs + 64 * 64;
  float* Vs  = Ks + 64 * 64;
  float* Es  = Vs + 64 * 64;
  float* Ss  = Es + 128 * 64;
  float* m_s = Ss + 64 * SSTR;
  float* l_s = m_s + 64;
  float* cf  = l_s + 64;

  const int tid = threadIdx.x;
  const int tb = gridDim.x - 1 - blockIdx.x;
  const int h = blockIdx.y, b = blockIdx.z;
  const int t0 = tb * 64;
  const int ty = tid >> 4, tx = tid & 15;
  const int tloc = ty * 4;
  const int cloc = tx * 4;

#pragma unroll
  for (int i = 0; i < 16; i++) {
    int lin = i * 256 + tid;
    int t = lin >> 6, kk = lin & 63;
    Qs[swz(t, kk)] = qkv[(b * TSEQ + t0 + t) * (3 * CDIM) + h * 64 + kk];
  }
  if (tid < 64) { m_s[tid] = -1e30f; l_s[tid] = 0.f; }

  u64 accO2[4][2];
#pragma unroll
  for (int i = 0; i < 4; i++) { accO2[i][0] = 0ull; accO2[i][1] = 0ull; }

  for (int sb = 0; sb <= tb; sb++) {
    const int s0 = sb * 64;
    const int diff = t0 - s0;
    __syncthreads();

#pragma unroll
    for (int i = 0; i < 16; i++) {
      int lin = i * 256 + tid;
      int s = lin >> 6, kk = lin & 63;
      int off = (b * TSEQ + s0 + s) * (3 * CDIM) + h * 64 + kk;
      Ks[swz(s, kk)] = qkv[off + CDIM] * 0.125f;
      Vs[swz(s, kk)] = qkv[off + 2 * CDIM];
    }
#pragma unroll
    for (int i = 0; i < 32; i++) {
      int lin = i * 256 + tid;
      int j = lin >> 6, kk = lin & 63;
      int rel = diff - 63 + j;
      bool ok = (rel >= 0) && (rel < TSEQ);
      Es[swz(j, kk)] = ok ? embk[rel * 64 + kk] : 0.f;
    }
    __syncthreads();

    u64 acc2[4][4];
#pragma unroll
    for (int i = 0; i < 4; i++)
#pragma unroll
      for (int j = 0; j < 4; j++) acc2[i][j] = 0ull;

    const int ebase = tloc - cloc + 60;
#pragma unroll 4
    for (int kk = 0; kk < 64; kk += 4) {
      ulonglong2 qd[4], kd[4], ed[7];
#pragma unroll
      for (int i = 0; i < 4; i++) qd[i] = *(ulonglong2*)&Qs[swz(tloc + i, kk)];
#pragma unroll
      for (int j = 0; j < 4; j++) kd[j] = *(ulonglong2*)&Ks[swz(cloc + j, kk)];
#pragma unroll
      for (int m = 0; m < 7; m++) ed[m] = *(ulonglong2*)&Es[swz(ebase + m, kk)];
#pragma unroll
      for (int i = 0; i < 4; i++)
#pragma unroll
        for (int j = 0; j < 4; j++) {
          ulonglong2 e2 = ed[i - j + 3];
          acc2[i][j] = ffma2(qd[i].x, fadd2(kd[j].x, e2.x), acc2[i][j]);
          acc2[i][j] = ffma2(qd[i].y, fadd2(kd[j].y, e2.y), acc2[i][j]);
        }
    }
#pragma unroll
    for (int i = 0; i < 4; i++) {
      float sv[4];
#pragma unroll
      for (int j = 0; j < 4; j++) {
        float lo, hi; funpack2(lo, hi, acc2[i][j]);
        bool masked = (sb == tb) && (cloc + j > tloc + i);
        sv[j] = masked ? -1e30f : (lo + hi);
      }
      *(float4*)&Ss[(tloc + i) * SSTR + cloc] = *(float4*)sv;
    }
    __syncthreads();

    {
      const int r = tid >> 2, q = tid & 3;
      float* row = &Ss[r * SSTR + q * 16];
      float4 v0 = *(float4*)&row[0],  v1 = *(float4*)&row[4];
      float4 v2 = *(float4*)&row[8],  v3 = *(float4*)&row[12];
      float mx = fmaxf(fmaxf(fmaxf(v0.x, v0.y), fmaxf(v0.z, v0.w)),
                       fmaxf(fmaxf(v1.x, v1.y), fmaxf(v1.z, v1.w)));
      mx = fmaxf(mx, fmaxf(fmaxf(fmaxf(v2.x, v2.y), fmaxf(v2.z, v2.w)),
                           fmaxf(fmaxf(v3.x, v3.y), fmaxf(v3.z, v3.w))));
      mx = fmaxf(mx, __shfl_xor_sync(0xffffffffu, mx, 1));
      mx = fmaxf(mx, __shfl_xor_sync(0xffffffffu, mx, 2));
      float mold = m_s[r];
      mx = fmaxf(mx, mold);
      v0.x = __expf(v0.x - mx); v0.y = __expf(v0.y - mx);
      v0.z = __expf(v0.z - mx); v0.w = __expf(v0.w - mx);
      v1.x = __expf(v1.x - mx); v1.y = __expf(v1.y - mx);
      v1.z = __expf(v1.z - mx); v1.w = __expf(v1.w - mx);
      v2.x = __expf(v2.x - mx); v2.y = __expf(v2.y - mx);
      v2.z = __expf(v2.z - mx); v2.w = __expf(v2.w - mx);
      v3.x = __expf(v3.x - mx); v3.y = __expf(v3.y - mx);
      v3.z = __expf(v3.z - mx); v3.w = __expf(v3.w - mx);
      *(float4*)&row[0] = v0;  *(float4*)&row[4] = v1;
      *(float4*)&row[8] = v2;  *(float4*)&row[12] = v3;
      float sum = v0.x + v0.y + v0.z + v0.w + v1.x + v1.y + v1.z + v1.w
                + v2.x + v2.y + v2.z + v2.w + v3.x + v3.y + v3.z + v3.w;
      sum += __shfl_xor_sync(0xffffffffu, sum, 1);
      sum += __shfl_xor_sync(0xffffffffu, sum, 2);
      if (q == 0) {
        float c = __expf(mold - mx);
        m_s[r] = mx;
        l_s[r] = l_s[r] * c + sum;
        cf[r] = c;
      }
    }
#pragma unroll
    for (int i = 0; i < 32; i++) {
      int lin = i * 256 + tid;
      int j = lin >> 6, kk = lin & 63;
      int rel = diff - 63 + j;
      bool ok = (rel >= 0) && (rel < TSEQ);
      Es[swz(j, kk)] = ok ? embv[rel * 64 + kk] : 0.f;
    }
    __syncthreads();

#pragma unroll
    for (int i = 0; i < 4; i++) {
      u64 cd = fpack2(cf[tloc + i], cf[tloc + i]);
      accO2[i][0] = fmul2(accO2[i][0], cd);
      accO2[i][1] = fmul2(accO2[i][1], cd);
    }
#pragma unroll 4
    for (int s = 0; s < 64; s++) {
      ulonglong2 vd = *(ulonglong2*)&Vs[swz(s, cloc)];
      float p[4];
#pragma unroll
      for (int i = 0; i < 4; i++) p[i] = Ss[(tloc + i) * SSTR + s];
#pragma unroll
      for (int i = 0; i < 4; i++) {
        ulonglong2 evd = *(ulonglong2*)&Es[swz(tloc + i - s + 63, cloc)];
        u64 pd = fpack2(p[i], p[i]);
        accO2[i][0] = ffma2(pd, fadd2(vd.x, evd.x), accO2[i][0]);
        accO2[i][1] = ffma2(pd, fadd2(vd.y, evd.y), accO2[i][1]);
      }
    }
  }

#pragma unroll
  for (int i = 0; i < 4; i++) {
    float linv = 1.f / l_s[tloc + i];
    float o[4];
    funpack2(o[0], o[1], accO2[i][0]);
    funpack2(o[2], o[3], accO2[i][1]);
    float4 ov = make_float4(o[0] * linv, o[1] * linv, o[2] * linv, o[3] * linv);
    *(float4*)&y[(b * TSEQ + t0 + tloc + i) * CDIM + h * 64 + cloc] = ov;
  }
}

// ---------------------------------------------------------------------------
extern "C" void kernel_launch(void* const* d_in, const int* in_sizes, int n_in,
                              void* d_out, int out_size) {
  const float* x      = (const float*)d_in[0];
  const float* w_attn = (const float*)d_in[1];
  const float* w_proj = (const float*)d_in[2];
  const float* embk   = (const float*)d_in[3];
  const float* embv   = (const float*)d_in[4];
  float* out = (float*)d_out;

  float *qkv, *y;
  __nv_bfloat16 *xh, *xl, *wah, *wal, *wph, *wpl, *yh, *yl;
  cudaGetSymbolAddress((void**)&qkv, g_qkv);
  cudaGetSymbolAddress((void**)&y,   g_y);
  cudaGetSymbolAddress((void**)&xh,  g_xh);  cudaGetSymbolAddress((void**)&xl, g_xl);
  cudaGetSymbolAddress((void**)&wah, g_wah); cudaGetSymbolAddress((void**)&wal, g_wal);
  cudaGetSymbolAddress((void**)&wph, g_wph); cudaGetSymbolAddress((void**)&wpl, g_wpl);
  cudaGetSymbolAddress((void**)&yh,  g_yh);  cudaGetSymbolAddress((void**)&yl, g_yl);

  const int M = BSZ * TSEQ;          // 4096
  const int n4 = M * CDIM / 4;

  split_kernel<<<(n4 + 255) / 256, 256>>>(x, xh, xl, n4);
  splitT_kernel<<<dim3(3 * CDIM / 32, CDIM / 32), dim3(32, 8)>>>(w_attn, wah, wal,
                                                                 CDIM, 3 * CDIM);
  splitT_kernel<<<dim3(CDIM / 32, CDIM / 32), dim3(32, 8)>>>(w_proj, wph, wpl,
                                                             CDIM, CDIM);

  cudaFuncSetAttribute(gemm_kernel,
                       cudaFuncAttributeMaxDynamicSharedMemorySize, G_SMEM);
  // QKV: [4096,1024] @ [1024,3072]
  gemm_kernel<<<dim3(3 * CDIM / 128, M / 128), 256, G_SMEM>>>(
      xh, xl, wah, wal, x, w_attn, qkv, M, 3 * CDIM, CDIM);

  cudaFuncSetAttribute(attn_kernel, cudaFuncAttributeMaxDynamicSharedMemorySize,
                       ATT_SMEM_BYTES);
  attn_kernel<<<dim3(TSEQ / 64, NHEAD, BSZ), 256, ATT_SMEM_BYTES>>>(qkv, embk,
                                                                    embv, y);

  split_kernel<<<(n4 + 255) / 256, 256>>>(y, yh, yl, n4);
  // Projection: [4096,1024] @ [1024,1024]
  gemm_kernel<<<dim3(CDIM / 128, M / 128), 256, G_SMEM>>>(
      yh, yl, wph, wpl, y, w_proj, out, M, CDIM, CDIM);
}

// round 8
// speedup vs baseline: 4.0682x; 1.0946x over previous
#include <cuda_runtime.h>
#include <cuda_bf16.h>
#include <math.h>

#define BSZ   4
#define TSEQ  1024
#define CDIM  1024
#define NHEAD 16
#define DHEAD 64

typedef unsigned long long u64;

#if defined(__CUDA_ARCH_FEAT_SM103_ALL) || \
    (defined(__CUDA_ARCH_SPECIFIC__) && (__CUDA_ARCH_SPECIFIC__ == 1030))
#define HAS_TCGEN05 1
#else
#define HAS_TCGEN05 0
#endif

// ---------------- scratch (allocation-free: __device__ globals) -------------
__device__ float g_qkv[BSZ * TSEQ * 3 * CDIM];   // [B,T,3C] fp32
__device__ float g_y[BSZ * TSEQ * CDIM];         // [B,T,C] fp32
__device__ __nv_bfloat16 g_xh[BSZ * TSEQ * CDIM], g_xl[BSZ * TSEQ * CDIM];
__device__ __nv_bfloat16 g_wah[3 * CDIM * CDIM], g_wal[3 * CDIM * CDIM]; // [N,K]
__device__ __nv_bfloat16 g_wph[CDIM * CDIM],     g_wpl[CDIM * CDIM];     // [N,K]
__device__ __nv_bfloat16 g_yh[BSZ * TSEQ * CDIM], g_yl[BSZ * TSEQ * CDIM];

// ---------------- packed f32x2 helpers --------------------------------------
__device__ __forceinline__ u64 ffma2(u64 a, u64 b, u64 c) {
  u64 d; asm("fma.rn.f32x2 %0, %1, %2, %3;" : "=l"(d) : "l"(a), "l"(b), "l"(c));
  return d;
}
__device__ __forceinline__ u64 fadd2(u64 a, u64 b) {
  u64 d; asm("add.rn.f32x2 %0, %1, %2;" : "=l"(d) : "l"(a), "l"(b));
  return d;
}
__device__ __forceinline__ u64 fmul2(u64 a, u64 b) {
  u64 d; asm("mul.rn.f32x2 %0, %1, %2;" : "=l"(d) : "l"(a), "l"(b));
  return d;
}
__device__ __forceinline__ u64 fpack2(float lo, float hi) {
  u64 d; asm("mov.b64 %0, {%1, %2};" : "=l"(d) : "f"(lo), "f"(hi));
  return d;
}
__device__ __forceinline__ void funpack2(float& lo, float& hi, u64 d) {
  asm("mov.b64 {%0, %1}, %2;" : "=f"(lo), "=f"(hi) : "l"(d));
}

// ---------------- generic plumbing (legal on all targets) -------------------
__device__ __forceinline__ unsigned smem_u32(const void* p) {
  unsigned a;
  asm("{ .reg .u64 t; cvta.to.shared.u64 t, %1; cvt.u32.u64 %0, t; }"
      : "=r"(a) : "l"(p));
  return a;
}
__device__ __forceinline__ unsigned elect_one() {
  unsigned p;
  asm volatile("{ .reg .pred P; elect.sync _|P, 0xFFFFFFFF; selp.b32 %0,1,0,P; }"
               : "=r"(p));
  return p;
}
__device__ __forceinline__ void cp_async16(unsigned dst, const void* src) {
  asm volatile("cp.async.cg.shared.global [%0], [%1], 16;"
               :: "r"(dst), "l"(src) : "memory");
}
#define CP_COMMIT() asm volatile("cp.async.commit_group;" ::: "memory")
#define CP_WAIT(n)  asm volatile("cp.async.wait_group %0;" :: "n"(n) : "memory")

__device__ __forceinline__ void mbar_init(unsigned a, unsigned cnt) {
  asm volatile("mbarrier.init.shared.b64 [%0], %1;" :: "r"(a), "r"(cnt) : "memory");
}
__device__ __forceinline__ void mbar_wait(unsigned a, unsigned phase) {
  asm volatile(
      "{\n\t.reg .pred P;\n\t"
      "W_%=:\n\t"
      "mbarrier.try_wait.parity.acquire.cta.shared::cta.b64 P, [%0], %1, 0x989680;\n\t"
      "@!P bra W_%=;\n\t}"
      :: "r"(a), "r"(phase) : "memory");
}

#define SWZ128(o) ((o) ^ (((o) >> 3) & 0x70))
__device__ __forceinline__ u64 make_desc(unsigned addr) {
  const u64 base = (2ull << 61) | (1ull << 46) | (64ull << 32) | (1ull << 16);
  return base | ((u64)(addr >> 4) & 0x3FFF);
}
// idesc: c=F32, a=BF16, b=BF16, M=128, N=128
#define GEMM_IDESC ((1u<<4)|(1u<<7)|(1u<<10)|((128u/8)<<17)|((128u/16)<<24))

// ---------------- tcgen05 wrappers (only compiled on sm_103a pass) ----------
#if HAS_TCGEN05
__device__ __forceinline__ void tmem_alloc(unsigned smem_dst, unsigned ncols) {
  asm volatile("tcgen05.alloc.cta_group::1.sync.aligned.shared::cta.b32 [%0], %1;"
               :: "r"(smem_dst), "r"(ncols) : "memory");
}
__device__ __forceinline__ void tmem_dealloc(unsigned tmem, unsigned ncols) {
  asm volatile("tcgen05.dealloc.cta_group::1.sync.aligned.b32 %0, %1;"
               :: "r"(tmem), "r"(ncols));
}
__device__ __forceinline__ void tmem_relinquish() {
  asm volatile("tcgen05.relinquish_alloc_permit.cta_group::1.sync.aligned;");
}
__device__ __forceinline__ void tc_commit(unsigned mbar) {
  asm volatile(
      "tcgen05.commit.cta_group::1.mbarrier::arrive::one.shared::cluster.b64 [%0];"
      :: "r"(mbar) : "memory");
}
#define TC_FENCE_AFTER()  asm volatile("tcgen05.fence::after_thread_sync;" ::: "memory")
#define TC_WAIT_LD()      asm volatile("tcgen05.wait::ld.sync.aligned;" ::: "memory")

__device__ __forceinline__ void mma_f16_ss(unsigned d_tmem, u64 a_desc, u64 b_desc,
                                           unsigned idesc, unsigned enable) {
  asm volatile(
      "{\n\t.reg .pred p;\n\tsetp.ne.u32 p, %4, 0;\n\t"
      "tcgen05.mma.cta_group::1.kind::f16 [%0], %1, %2, %3, {%5,%5,%5,%5}, p;\n\t}"
      :: "r"(d_tmem), "l"(a_desc), "l"(b_desc), "r"(idesc), "r"(enable), "r"(0u)
      : "memory");
}
__device__ __forceinline__ void tmem_ld32(unsigned* r, unsigned addr) {
  asm volatile(
      "tcgen05.ld.sync.aligned.32x32b.x32.b32 "
      "{%0,%1,%2,%3,%4,%5,%6,%7,%8,%9,%10,%11,%12,%13,%14,%15,"
      "%16,%17,%18,%19,%20,%21,%22,%23,%24,%25,%26,%27,%28,%29,%30,%31}, [%32];"
      : "=r"(r[0]),"=r"(r[1]),"=r"(r[2]),"=r"(r[3]),"=r"(r[4]),"=r"(r[5]),
        "=r"(r[6]),"=r"(r[7]),"=r"(r[8]),"=r"(r[9]),"=r"(r[10]),"=r"(r[11]),
        "=r"(r[12]),"=r"(r[13]),"=r"(r[14]),"=r"(r[15]),"=r"(r[16]),"=r"(r[17]),
        "=r"(r[18]),"=r"(r[19]),"=r"(r[20]),"=r"(r[21]),"=r"(r[22]),"=r"(r[23]),
        "=r"(r[24]),"=r"(r[25]),"=r"(r[26]),"=r"(r[27]),"=r"(r[28]),"=r"(r[29]),
        "=r"(r[30]),"=r"(r[31])
      : "r"(addr));
}
#endif  // HAS_TCGEN05

// ---------------------------------------------------------------------------
// Unified GEMM (unchanged from R7): tcgen05 bf16x3 on sm_103a, FFMA2 fallback.
// ---------------------------------------------------------------------------
#define G_TILE  (128 * 64 * 2)
#define G_BUF   (4 * G_TILE)
#define G_SMEM  (1024 + 2 * G_BUF)

__global__ void __launch_bounds__(256) gemm_kernel(
    const __nv_bfloat16* __restrict__ Ah, const __nv_bfloat16* __restrict__ Al,
    const __nv_bfloat16* __restrict__ Bh, const __nv_bfloat16* __restrict__ Bl,
    const float* __restrict__ Af, const float* __restrict__ Bf,
    float* __restrict__ C, int M, int N, int K) {
  extern __shared__ char smem[];
  const int tid = threadIdx.x;
  const int brow = blockIdx.y * 128, bcol = blockIdx.x * 128;

#if HAS_TCGEN05
  const unsigned sb = smem_u32(smem);
  const int wid = tid >> 5, lid = tid & 31;
  const int NKT = K >> 6;
  const unsigned mb0 = sb + 16, mb1 = sb + 24;
  const unsigned tiles = sb + 1024;

  if (tid == 0) { mbar_init(mb0, 1); mbar_init(mb1, 1); }
  if (wid == 0) { tmem_alloc(sb, 128); tmem_relinquish(); }
  __syncthreads();
  unsigned tmem;
  asm volatile("ld.shared.b32 %0, [%1];" : "=r"(tmem) : "r"(sb));

  const __nv_bfloat16* srcs[4] = {Ah, Al, Bh, Bl};
  const int rb[4] = {brow, brow, bcol, bcol};

  auto stage = [&](int buf, int kt) {
#pragma unroll
    for (int t = 0; t < 4; t++) {
      const __nv_bfloat16* s = srcs[t] + (size_t)rb[t] * K + kt * 64;
      unsigned tb = tiles + buf * G_BUF + t * G_TILE;
#pragma unroll
      for (int it = 0; it < 4; it++) {
        int i = it * 256 + tid;
        int r = i >> 3, c = i & 7;
        cp_async16(tb + SWZ128(r * 128 + c * 16), s + (size_t)r * K + c * 8);
      }
    }
  };

  stage(0, 0);
  CP_COMMIT();
  int ph0 = 0, ph1 = 0;

  for (int kt = 0; kt < NKT; kt++) {
    const int buf = kt & 1;
    if (kt > 0) {
      if (((kt - 1) & 1) == 0) { mbar_wait(mb0, ph0 & 1); ph0++; }
      else                     { mbar_wait(mb1, ph1 & 1); ph1++; }
    }
    if (kt + 1 < NKT) { stage(buf ^ 1, kt + 1); CP_COMMIT(); CP_WAIT(1); }
    else              { CP_WAIT(0); }
    __syncthreads();

    if (wid == 0 && elect_one()) {
      asm volatile("fence.proxy.async.shared::cta;" ::: "memory");
      unsigned base = tiles + buf * G_BUF;
      u64 dAh = make_desc(base),              dAl = make_desc(base + G_TILE);
      u64 dBh = make_desc(base + 2 * G_TILE), dBl = make_desc(base + 3 * G_TILE);
      u64 da[3] = {dAh, dAl, dAh};
      u64 db[3] = {dBh, dBh, dBl};
#pragma unroll
      for (int p = 0; p < 3; p++)
#pragma unroll
        for (int ks = 0; ks < 4; ks++)
          mma_f16_ss(tmem, da[p] + ks * 2, db[p] + ks * 2, GEMM_IDESC,
                     !(kt == 0 && p == 0 && ks == 0));
      tc_commit(buf == 0 ? mb0 : mb1);
    }
  }
  if (((NKT - 1) & 1) == 0) { mbar_wait(mb0, ph0 & 1); }
  else                      { mbar_wait(mb1, ph1 & 1); }
  TC_FENCE_AFTER();

  if (wid < 4) {
    const size_t row = (size_t)brow + wid * 32 + lid;
#pragma unroll
    for (int cb = 0; cb < 128; cb += 32) {
      unsigned r[32];
      tmem_ld32(r, tmem + cb);
      TC_WAIT_LD();
      float* dst = &C[row * N + bcol + cb];
#pragma unroll
      for (int c = 0; c < 32; c += 4)
        *(float4*)&dst[c] = make_float4(__uint_as_float(r[c]), __uint_as_float(r[c+1]),
                                        __uint_as_float(r[c+2]), __uint_as_float(r[c+3]));
    }
  }
  __syncthreads();
  if (wid == 0) tmem_dealloc(tmem, 128);

#else  // fallback: fp32 FFMA2 SGEMM
  float (*As)[16][132] = reinterpret_cast<float(*)[16][132]>(smem);
  float (*Bs)[16][132] = reinterpret_cast<float(*)[16][132]>(smem + 2 * 16 * 132 * 4);
  const int ty = tid >> 4, tx = tid & 15;
  const int ar0 = tid >> 2,          ac0 = (tid & 3) * 4;
  const int ar1 = (tid + 256) >> 2,  ac1 = ((tid + 256) & 3) * 4;
  const int br0 = tid >> 5,          bc0 = (tid & 31) * 4;
  const int br1 = (tid + 256) >> 5,  bc1 = ((tid + 256) & 31) * 4;

  u64 acc2[8][4];
#pragma unroll
  for (int i = 0; i < 8; i++)
#pragma unroll
    for (int j = 0; j < 4; j++) acc2[i][j] = 0ull;

  {
    float4 a0 = *(const float4*)&Af[(size_t)(brow + ar0) * K + ac0];
    float4 a1 = *(const float4*)&Af[(size_t)(brow + ar1) * K + ac1];
    As[0][ac0 + 0][ar0] = a0.x; As[0][ac0 + 1][ar0] = a0.y;
    As[0][ac0 + 2][ar0] = a0.z; As[0][ac0 + 3][ar0] = a0.w;
    As[0][ac1 + 0][ar1] = a1.x; As[0][ac1 + 1][ar1] = a1.y;
    As[0][ac1 + 2][ar1] = a1.z; As[0][ac1 + 3][ar1] = a1.w;
    *(float4*)&Bs[0][br0][bc0] = *(const float4*)&Bf[(size_t)br0 * N + bcol + bc0];
    *(float4*)&Bs[0][br1][bc1] = *(const float4*)&Bf[(size_t)br1 * N + bcol + bc1];
  }
  __syncthreads();

  int buf = 0;
  for (int k0 = 0; k0 < K; k0 += 16) {
    const bool has_next = (k0 + 16) < K;
    float4 pa0, pa1, pb0, pb1;
    if (has_next) {
      pa0 = *(const float4*)&Af[(size_t)(brow + ar0) * K + k0 + 16 + ac0];
      pa1 = *(const float4*)&Af[(size_t)(brow + ar1) * K + k0 + 16 + ac1];
      pb0 = *(const float4*)&Bf[(size_t)(k0 + 16 + br0) * N + bcol + bc0];
      pb1 = *(const float4*)&Bf[(size_t)(k0 + 16 + br1) * N + bcol + bc1];
    }
#pragma unroll
    for (int kk = 0; kk < 16; kk++) {
      float a[8];
      *(float4*)&a[0] = *(float4*)&As[buf][kk][ty * 8];
      *(float4*)&a[4] = *(float4*)&As[buf][kk][ty * 8 + 4];
      u64 b2[4];
      *(ulonglong2*)&b2[0] = *(ulonglong2*)&Bs[buf][kk][tx * 4];
      *(ulonglong2*)&b2[2] = *(ulonglong2*)&Bs[buf][kk][64 + tx * 4];
      u64 ad[8];
#pragma unroll
      for (int i = 0; i < 8; i++) ad[i] = fpack2(a[i], a[i]);
#pragma unroll
      for (int i = 0; i < 8; i++)
#pragma unroll
        for (int j = 0; j < 4; j++) acc2[i][j] = ffma2(ad[i], b2[j], acc2[i][j]);
    }
    if (has_next) {
      int nb = buf ^ 1;
      As[nb][ac0 + 0][ar0] = pa0.x; As[nb][ac0 + 1][ar0] = pa0.y;
      As[nb][ac0 + 2][ar0] = pa0.z; As[nb][ac0 + 3][ar0] = pa0.w;
      As[nb][ac1 + 0][ar1] = pa1.x; As[nb][ac1 + 1][ar1] = pa1.y;
      As[nb][ac1 + 2][ar1] = pa1.z; As[nb][ac1 + 3][ar1] = pa1.w;
      *(float4*)&Bs[nb][br0][bc0] = pb0;
      *(float4*)&Bs[nb][br1][bc1] = pb1;
      __syncthreads();
      buf = nb;
    }
  }
#pragma unroll
  for (int i = 0; i < 8; i++) {
    size_t r = (size_t)(brow + ty * 8 + i) * N + bcol;
    *(ulonglong2*)&C[r + tx * 4]      = make_ulonglong2(acc2[i][0], acc2[i][1]);
    *(ulonglong2*)&C[r + 64 + tx * 4] = make_ulonglong2(acc2[i][2], acc2[i][3]);
  }
#endif
}

// ---------------------------------------------------------------------------
__global__ void __launch_bounds__(256) split_kernel(
    const float* __restrict__ src, __nv_bfloat16* __restrict__ h,
    __nv_bfloat16* __restrict__ l, int n4) {
  int i = blockIdx.x * 256 + threadIdx.x;
  if (i >= n4) return;
  float4 v = ((const float4*)src)[i];
  __nv_bfloat16 h0 = __float2bfloat16_rn(v.x), h1 = __float2bfloat16_rn(v.y);
  __nv_bfloat16 h2 = __float2bfloat16_rn(v.z), h3 = __float2bfloat16_rn(v.w);
  __nv_bfloat16 l0 = __float2bfloat16_rn(v.x - __bfloat162float(h0));
  __nv_bfloat16 l1 = __float2bfloat16_rn(v.y - __bfloat162float(h1));
  __nv_bfloat16 l2 = __float2bfloat16_rn(v.z - __bfloat162float(h2));
  __nv_bfloat16 l3 = __float2bfloat16_rn(v.w - __bfloat162float(h3));
  ((__nv_bfloat162*)h)[i * 2]     = __nv_bfloat162(h0, h1);
  ((__nv_bfloat162*)h)[i * 2 + 1] = __nv_bfloat162(h2, h3);
  ((__nv_bfloat162*)l)[i * 2]     = __nv_bfloat162(l0, l1);
  ((__nv_bfloat162*)l)[i * 2 + 1] = __nv_bfloat162(l2, l3);
}

__global__ void __launch_bounds__(256) splitT_kernel(
    const float* __restrict__ w, __nv_bfloat16* __restrict__ h,
    __nv_bfloat16* __restrict__ l, int K, int N) {
  __shared__ float t[32][33];
  int n0 = blockIdx.x * 32, k0 = blockIdx.y * 32;
  int tx = threadIdx.x, ty = threadIdx.y;
#pragma unroll
  for (int i = 0; i < 32; i += 8)
    t[ty + i][tx] = w[(size_t)(k0 + ty + i) * N + n0 + tx];
  __syncthreads();
#pragma unroll
  for (int i = 0; i < 32; i += 8) {
    float v = t[tx][ty + i];
    __nv_bfloat16 hh = __float2bfloat16_rn(v);
    __nv_bfloat16 ll = __float2bfloat16_rn(v - __bfloat162float(hh));
    size_t o = (size_t)(n0 + ty + i) * K + k0 + tx;
    h[o] = hh; l[o] = ll;
  }
}

// ---------------------------------------------------------------------------
// Flash attention with RPE. R8 changes:
//  - P written TRANSPOSED into the dead Ks buffer (PT[s][t]); O-phase P read
//    is one broadcast float4 per s.
//  - O phase iterates s descending with a rolling 4-row Ev register window:
//    1 new 16B load per s instead of 4.
//  - float4-vectorized staging for Q/K/V/E.
// ---------------------------------------------------------------------------
__device__ __forceinline__ int swz(int r, int kk) {
  return r * 64 + ((((kk >> 2) ^ (r >> 2)) & 15) << 2) + (kk & 3);
}

#define SSTR 68
#define ATT_SMEM_FLOATS (3 * 64 * 64 + 128 * 64 + 64 * SSTR + 3 * 64)
#define ATT_SMEM_BYTES  (ATT_SMEM_FLOATS * 4)

__global__ void __launch_bounds__(256, 2) attn_kernel(
    const float* __restrict__ qkv, const float* __restrict__ embk,
    const float* __restrict__ embv, float* __restrict__ y) {
  extern __shared__ float sm[];
  float* Qs  = sm;                  // 64 x 64 swizzled
  float* Ks  = sm + 64 * 64;        // 64 x 64 swizzled (K, then PT = P^T)
  float* Vs  = sm + 2 * 64 * 64;    // 64 x 64 swizzled
  float* Es  = sm + 3 * 64 * 64;    // 128 x 64 swizzled (embk then embv)
  float* Ss  = sm + 3 * 64 * 64 + 128 * 64;  // 64 x 68 plain (scores only)
  float* m_s = Ss + 64 * SSTR;
  float* l_s = m_s + 64;
  float* cf  = l_s + 64;

  const int tid = threadIdx.x;
  const int tb = gridDim.x - 1 - blockIdx.x;   // heavy blocks first
  const int h = blockIdx.y, b = blockIdx.z;
  const int t0 = tb * 64;
  const int ty = tid >> 4, tx = tid & 15;
  const int tloc = ty * 4;
  const int cloc = tx * 4;

  // Load Q tile (vectorized: 4 float4 per thread)
#pragma unroll
  for (int it = 0; it < 4; it++) {
    int g = it * 256 + tid;
    int t = g >> 4, kc = (g & 15) << 2;
    *(float4*)&Qs[swz(t, kc)] =
        *(const float4*)&qkv[(b * TSEQ + t0 + t) * (3 * CDIM) + h * 64 + kc];
  }
  if (tid < 64) { m_s[tid] = -1e30f; l_s[tid] = 0.f; }

  u64 accO2[4][2];
#pragma unroll
  for (int i = 0; i < 4; i++) { accO2[i][0] = 0ull; accO2[i][1] = 0ull; }

  for (int sb = 0; sb <= tb; sb++) {
    const int s0 = sb * 64;
    const int diff = t0 - s0;
    __syncthreads();   // prior O-phase reads (Vs/Es/PT) done

    // stage K (pre-scaled) and V, vectorized
#pragma unroll
    for (int it = 0; it < 4; it++) {
      int g = it * 256 + tid;
      int s = g >> 4, kc = (g & 15) << 2;
      const float* src = &qkv[(b * TSEQ + s0 + s) * (3 * CDIM) + h * 64 + kc];
      float4 kv = *(const float4*)(src + CDIM);
      float4 vv = *(const float4*)(src + 2 * CDIM);
      kv.x *= 0.125f; kv.y *= 0.125f; kv.z *= 0.125f; kv.w *= 0.125f;
      *(float4*)&Ks[swz(s, kc)] = kv;
      *(float4*)&Vs[swz(s, kc)] = vv;
    }
    // stage embk rows (vectorized): row j = embk[diff-63+j]
#pragma unroll
    for (int it = 0; it < 8; it++) {
      int g = it * 256 + tid;
      int j = g >> 4, kc = (g & 15) << 2;
      int rel = diff - 63 + j;
      float4 v = make_float4(0.f, 0.f, 0.f, 0.f);
      if (rel >= 0 && rel < TSEQ) v = *(const float4*)&embk[rel * 64 + kc];
      *(float4*)&Es[swz(j, kc)] = v;
    }
    __syncthreads();

    // ---- S phase: S[t,s] = q . (k_scaled + embk[t-s]) ----
    u64 acc2[4][4];
#pragma unroll
    for (int i = 0; i < 4; i++)
#pragma unroll
      for (int j = 0; j < 4; j++) acc2[i][j] = 0ull;

    const int ebase = tloc - cloc + 60;
#pragma unroll 4
    for (int kk = 0; kk < 64; kk += 4) {
      ulonglong2 qd[4], kd[4], ed[7];
#pragma unroll
      for (int i = 0; i < 4; i++) qd[i] = *(ulonglong2*)&Qs[swz(tloc + i, kk)];
#pragma unroll
      for (int j = 0; j < 4; j++) kd[j] = *(ulonglong2*)&Ks[swz(cloc + j, kk)];
#pragma unroll
      for (int m = 0; m < 7; m++) ed[m] = *(ulonglong2*)&Es[swz(ebase + m, kk)];
#pragma unroll
      for (int i = 0; i < 4; i++)
#pragma unroll
        for (int j = 0; j < 4; j++) {
          ulonglong2 e2 = ed[i - j + 3];
          acc2[i][j] = ffma2(qd[i].x, fadd2(kd[j].x, e2.x), acc2[i][j]);
          acc2[i][j] = ffma2(qd[i].y, fadd2(kd[j].y, e2.y), acc2[i][j]);
        }
    }
#pragma unroll
    for (int i = 0; i < 4; i++) {
      float sv[4];
#pragma unroll
      for (int j = 0; j < 4; j++) {
        float lo, hi; funpack2(lo, hi, acc2[i][j]);
        bool masked = (sb == tb) && (cloc + j > tloc + i);
        sv[j] = masked ? -1e30f : (lo + hi);
      }
      *(float4*)&Ss[(tloc + i) * SSTR + cloc] = *(float4*)sv;
    }
    __syncthreads();   // S phase done; Ks is now dead -> reuse as PT

    // ---- online softmax; write P TRANSPOSED into Ks (PT[s][t]) ----
    {
      const int r = tid >> 2, q = tid & 3;
      float* row = &Ss[r * SSTR + q * 16];
      float4 v0 = *(float4*)&row[0],  v1 = *(float4*)&row[4];
      float4 v2 = *(float4*)&row[8],  v3 = *(float4*)&row[12];
      float mx = fmaxf(fmaxf(fmaxf(v0.x, v0.y), fmaxf(v0.z, v0.w)),
                       fmaxf(fmaxf(v1.x, v1.y), fmaxf(v1.z, v1.w)));
      mx = fmaxf(mx, fmaxf(fmaxf(fmaxf(v2.x, v2.y), fmaxf(v2.z, v2.w)),
                           fmaxf(fmaxf(v3.x, v3.y), fmaxf(v3.z, v3.w))));
      mx = fmaxf(mx, __shfl_xor_sync(0xffffffffu, mx, 1));
      mx = fmaxf(mx, __shfl_xor_sync(0xffffffffu, mx, 2));
      float mold = m_s[r];
      mx = fmaxf(mx, mold);
      float e[16];
      e[0] = __expf(v0.x - mx);  e[1] = __expf(v0.y - mx);
      e[2] = __expf(v0.z - mx);  e[3] = __expf(v0.w - mx);
      e[4] = __expf(v1.x - mx);  e[5] = __expf(v1.y - mx);
      e[6] = __expf(v1.z - mx);  e[7] = __expf(v1.w - mx);
      e[8] = __expf(v2.x - mx);  e[9] = __expf(v2.y - mx);
      e[10] = __expf(v2.z - mx); e[11] = __expf(v2.w - mx);
      e[12] = __expf(v3.x - mx); e[13] = __expf(v3.y - mx);
      e[14] = __expf(v3.z - mx); e[15] = __expf(v3.w - mx);
      float sum = 0.f;
#pragma unroll
      for (int k = 0; k < 16; k++) {
        Ks[swz(q * 16 + k, r)] = e[k];   // PT[s][t]
        sum += e[k];
      }
      sum += __shfl_xor_sync(0xffffffffu, sum, 1);
      sum += __shfl_xor_sync(0xffffffffu, sum, 2);
      if (q == 0) {
        float c = __expf(mold - mx);
        m_s[r] = mx;
        l_s[r] = l_s[r] * c + sum;
        cf[r] = c;
      }
    }
    // stage embv rows (Es reuse), vectorized
#pragma unroll
    for (int it = 0; it < 8; it++) {
      int g = it * 256 + tid;
      int j = g >> 4, kc = (g & 15) << 2;
      int rel = diff - 63 + j;
      float4 v = make_float4(0.f, 0.f, 0.f, 0.f);
      if (rel >= 0 && rel < TSEQ) v = *(const float4*)&embv[rel * 64 + kc];
      *(float4*)&Es[swz(j, kc)] = v;
    }
    __syncthreads();

    // ---- O phase: O[t,e] += P[t,s] * (V[s,e] + embv[t-s][e]) ----
    // s descends; Ev rows (tloc+i-s+63) shift by 1 per step -> rolling window.
#pragma unroll
    for (int i = 0; i < 4; i++) {
      u64 cd = fpack2(cf[tloc + i], cf[tloc + i]);
      accO2[i][0] = fmul2(accO2[i][0], cd);
      accO2[i][1] = fmul2(accO2[i][1], cd);
    }
    ulonglong2 ew0 = *(ulonglong2*)&Es[swz(tloc + 0, cloc)];
    ulonglong2 ew1 = *(ulonglong2*)&Es[swz(tloc + 1, cloc)];
    ulonglong2 ew2 = *(ulonglong2*)&Es[swz(tloc + 2, cloc)];
    ulonglong2 ew3 = *(ulonglong2*)&Es[swz(tloc + 3, cloc)];
#pragma unroll 4
    for (int s5 = 0; s5 < 64; s5++) {
      const int s = 63 - s5;
      ulonglong2 vd = *(ulonglong2*)&Vs[swz(s, cloc)];
      float4 p4 = *(float4*)&Ks[swz(s, tloc)];   // PT broadcast
      u64 pd;
      pd = fpack2(p4.x, p4.x);
      accO2[0][0] = ffma2(pd, fadd2(vd.x, ew0.x), accO2[0][0]);
      accO2[0][1] = ffma2(pd, fadd2(vd.y, ew0.y), accO2[0][1]);
      pd = fpack2(p4.y, p4.y);
      accO2[1][0] = ffma2(pd, fadd2(vd.x, ew1.x), accO2[1][0]);
      accO2[1][1] = ffma2(pd, fadd2(vd.y, ew1.y), accO2[1][1]);
      pd = fpack2(p4.z, p4.z);
      accO2[2][0] = ffma2(pd, fadd2(vd.x, ew2.x), accO2[2][0]);
      accO2[2][1] = ffma2(pd, fadd2(vd.y, ew2.y), accO2[2][1]);
      pd = fpack2(p4.w, p4.w);
      accO2[3][0] = ffma2(pd, fadd2(vd.x, ew3.x), accO2[3][0]);
      accO2[3][1] = ffma2(pd, fadd2(vd.y, ew3.y), accO2[3][1]);
      // shift window; next iter needs top row tloc+4+s5 (always <= 127)
      ew0 = ew1; ew1 = ew2; ew2 = ew3;
      ew3 = *(ulonglong2*)&Es[swz(tloc + 4 + s5, cloc)];
    }
  }

  // epilogue
#pragma unroll
  for (int i = 0; i < 4; i++) {
    float linv = 1.f / l_s[tloc + i];
    float o[4];
    funpack2(o[0], o[1], accO2[i][0]);
    funpack2(o[2], o[3], accO2[i][1]);
    float4 ov = make_float4(o[0] * linv, o[1] * linv, o[2] * linv, o[3] * linv);
    *(float4*)&y[(b * TSEQ + t0 + tloc + i) * CDIM + h * 64 + cloc] = ov;
  }
}

// ---------------------------------------------------------------------------
extern "C" void kernel_launch(void* const* d_in, const int* in_sizes, int n_in,
                              void* d_out, int out_size) {
  const float* x      = (const float*)d_in[0];
  const float* w_attn = (const float*)d_in[1];
  const float* w_proj = (const float*)d_in[2];
  const float* embk   = (const float*)d_in[3];
  const float* embv   = (const float*)d_in[4];
  float* out = (float*)d_out;

  float *qkv, *y;
  __nv_bfloat16 *xh, *xl, *wah, *wal, *wph, *wpl, *yh, *yl;
  cudaGetSymbolAddress((void**)&qkv, g_qkv);
  cudaGetSymbolAddress((void**)&y,   g_y);
  cudaGetSymbolAddress((void**)&xh,  g_xh);  cudaGetSymbolAddress((void**)&xl, g_xl);
  cudaGetSymbolAddress((void**)&wah, g_wah); cudaGetSymbolAddress((void**)&wal, g_wal);
  cudaGetSymbolAddress((void**)&wph, g_wph); cudaGetSymbolAddress((void**)&wpl, g_wpl);
  cudaGetSymbolAddress((void**)&yh,  g_yh);  cudaGetSymbolAddress((void**)&yl, g_yl);

  const int M = BSZ * TSEQ;
  const int n4 = M * CDIM / 4;

  split_kernel<<<(n4 + 255) / 256, 256>>>(x, xh, xl, n4);
  splitT_kernel<<<dim3(3 * CDIM / 32, CDIM / 32), dim3(32, 8)>>>(w_attn, wah, wal,
                                                                 CDIM, 3 * CDIM);
  splitT_kernel<<<dim3(CDIM / 32, CDIM / 32), dim3(32, 8)>>>(w_proj, wph, wpl,
                                                             CDIM, CDIM);

  cudaFuncSetAttribute(gemm_kernel,
                       cudaFuncAttributeMaxDynamicSharedMemorySize, G_SMEM);
  gemm_kernel<<<dim3(3 * CDIM / 128, M / 128), 256, G_SMEM>>>(
      xh, xl, wah, wal, x, w_attn, qkv, M, 3 * CDIM, CDIM);

  cudaFuncSetAttribute(attn_kernel, cudaFuncAttributeMaxDynamicSharedMemorySize,
                       ATT_SMEM_BYTES);
  attn_kernel<<<dim3(TSEQ / 64, NHEAD, BSZ), 256, ATT_SMEM_BYTES>>>(qkv, embk,
                                                                    embv, y);

  split_kernel<<<(n4 + 255) / 256, 256>>>(y, yh, yl, n4);
  gemm_kernel<<<dim3(CDIM / 128, M / 128), 256, G_SMEM>>>(
      yh, yl, wph, wpl, y, w_proj, out, M, CDIM, CDIM);
}

// round 9
// speedup vs baseline: 4.2623x; 1.0477x over previous
#include <cuda_runtime.h>
#include <cuda_bf16.h>
#include <math.h>

#define BSZ   4
#define TSEQ  1024
#define CDIM  1024
#define NHEAD 16
#define DHEAD 64

typedef unsigned long long u64;

#if defined(__CUDA_ARCH_FEAT_SM103_ALL) || \
    (defined(__CUDA_ARCH_SPECIFIC__) && (__CUDA_ARCH_SPECIFIC__ == 1030))
#define HAS_TCGEN05 1
#else
#define HAS_TCGEN05 0
#endif

// ---------------- scratch (allocation-free: __device__ globals) -------------
__device__ float g_qkv[BSZ * TSEQ * 3 * CDIM];
__device__ float g_y[BSZ * TSEQ * CDIM];
__device__ __nv_bfloat16 g_xh[BSZ * TSEQ * CDIM], g_xl[BSZ * TSEQ * CDIM];
__device__ __nv_bfloat16 g_wah[3 * CDIM * CDIM], g_wal[3 * CDIM * CDIM]; // [N,K]
__device__ __nv_bfloat16 g_wph[CDIM * CDIM],     g_wpl[CDIM * CDIM];     // [N,K]
__device__ __nv_bfloat16 g_yh[BSZ * TSEQ * CDIM], g_yl[BSZ * TSEQ * CDIM];

// ---------------- packed f32x2 helpers --------------------------------------
__device__ __forceinline__ u64 ffma2(u64 a, u64 b, u64 c) {
  u64 d; asm("fma.rn.f32x2 %0, %1, %2, %3;" : "=l"(d) : "l"(a), "l"(b), "l"(c));
  return d;
}
__device__ __forceinline__ u64 fadd2(u64 a, u64 b) {
  u64 d; asm("add.rn.f32x2 %0, %1, %2;" : "=l"(d) : "l"(a), "l"(b));
  return d;
}
__device__ __forceinline__ u64 fmul2(u64 a, u64 b) {
  u64 d; asm("mul.rn.f32x2 %0, %1, %2;" : "=l"(d) : "l"(a), "l"(b));
  return d;
}
__device__ __forceinline__ u64 fpack2(float lo, float hi) {
  u64 d; asm("mov.b64 %0, {%1, %2};" : "=l"(d) : "f"(lo), "f"(hi));
  return d;
}
__device__ __forceinline__ void funpack2(float& lo, float& hi, u64 d) {
  asm("mov.b64 {%0, %1}, %2;" : "=f"(lo), "=f"(hi) : "l"(d));
}

// ---------------- generic plumbing ------------------------------------------
__device__ __forceinline__ unsigned smem_u32(const void* p) {
  unsigned a;
  asm("{ .reg .u64 t; cvta.to.shared.u64 t, %1; cvt.u32.u64 %0, t; }"
      : "=r"(a) : "l"(p));
  return a;
}
__device__ __forceinline__ unsigned elect_one() {
  unsigned p;
  asm volatile("{ .reg .pred P; elect.sync _|P, 0xFFFFFFFF; selp.b32 %0,1,0,P; }"
               : "=r"(p));
  return p;
}
__device__ __forceinline__ void cp_async16(unsigned dst, const void* src) {
  asm volatile("cp.async.cg.shared.global [%0], [%1], 16;"
               :: "r"(dst), "l"(src) : "memory");
}
#define CP_COMMIT() asm volatile("cp.async.commit_group;" ::: "memory")
#define CP_WAIT(n)  asm volatile("cp.async.wait_group %0;" :: "n"(n) : "memory")

__device__ __forceinline__ void mbar_init(unsigned a, unsigned cnt) {
  asm volatile("mbarrier.init.shared.b64 [%0], %1;" :: "r"(a), "r"(cnt) : "memory");
}
__device__ __forceinline__ void mbar_wait(unsigned a, unsigned phase) {
  asm volatile(
      "{\n\t.reg .pred P;\n\t"
      "W_%=:\n\t"
      "mbarrier.try_wait.parity.acquire.cta.shared::cta.b64 P, [%0], %1, 0x989680;\n\t"
      "@!P bra W_%=;\n\t}"
      :: "r"(a), "r"(phase) : "memory");
}

#define SWZ128(o) ((o) ^ (((o) >> 3) & 0x70))
__device__ __forceinline__ u64 make_desc(unsigned addr) {
  const u64 base = (2ull << 61) | (1ull << 46) | (64ull << 32) | (1ull << 16);
  return base | ((u64)(addr >> 4) & 0x3FFF);
}
// idesc: c=F32, a=BF16, b=BF16, M=128, N=256
#define GEMM_IDESC ((1u<<4)|(1u<<7)|(1u<<10)|((256u/8)<<17)|((128u/16)<<24))

// ---------------- tcgen05 wrappers (sm_103a pass only) ----------------------
#if HAS_TCGEN05
__device__ __forceinline__ void tmem_alloc(unsigned smem_dst, unsigned ncols) {
  asm volatile("tcgen05.alloc.cta_group::1.sync.aligned.shared::cta.b32 [%0], %1;"
               :: "r"(smem_dst), "r"(ncols) : "memory");
}
__device__ __forceinline__ void tmem_dealloc(unsigned tmem, unsigned ncols) {
  asm volatile("tcgen05.dealloc.cta_group::1.sync.aligned.b32 %0, %1;"
               :: "r"(tmem), "r"(ncols));
}
__device__ __forceinline__ void tmem_relinquish() {
  asm volatile("tcgen05.relinquish_alloc_permit.cta_group::1.sync.aligned;");
}
__device__ __forceinline__ void tc_commit(unsigned mbar) {
  asm volatile(
      "tcgen05.commit.cta_group::1.mbarrier::arrive::one.shared::cluster.b64 [%0];"
      :: "r"(mbar) : "memory");
}
#define TC_FENCE_AFTER()  asm volatile("tcgen05.fence::after_thread_sync;" ::: "memory")
#define TC_WAIT_LD()      asm volatile("tcgen05.wait::ld.sync.aligned;" ::: "memory")

__device__ __forceinline__ void mma_f16_ss(unsigned d_tmem, u64 a_desc, u64 b_desc,
                                           unsigned idesc, unsigned enable) {
  asm volatile(
      "{\n\t.reg .pred p;\n\tsetp.ne.u32 p, %4, 0;\n\t"
      "tcgen05.mma.cta_group::1.kind::f16 [%0], %1, %2, %3, {%5,%5,%5,%5}, p;\n\t}"
      :: "r"(d_tmem), "l"(a_desc), "l"(b_desc), "r"(idesc), "r"(enable), "r"(0u)
      : "memory");
}
__device__ __forceinline__ void tmem_ld32(unsigned* r, unsigned addr) {
  asm volatile(
      "tcgen05.ld.sync.aligned.32x32b.x32.b32 "
      "{%0,%1,%2,%3,%4,%5,%6,%7,%8,%9,%10,%11,%12,%13,%14,%15,"
      "%16,%17,%18,%19,%20,%21,%22,%23,%24,%25,%26,%27,%28,%29,%30,%31}, [%32];"
      : "=r"(r[0]),"=r"(r[1]),"=r"(r[2]),"=r"(r[3]),"=r"(r[4]),"=r"(r[5]),
        "=r"(r[6]),"=r"(r[7]),"=r"(r[8]),"=r"(r[9]),"=r"(r[10]),"=r"(r[11]),
        "=r"(r[12]),"=r"(r[13]),"=r"(r[14]),"=r"(r[15]),"=r"(r[16]),"=r"(r[17]),
        "=r"(r[18]),"=r"(r[19]),"=r"(r[20]),"=r"(r[21]),"=r"(r[22]),"=r"(r[23]),
        "=r"(r[24]),"=r"(r[25]),"=r"(r[26]),"=r"(r[27]),"=r"(r[28]),"=r"(r[29]),
        "=r"(r[30]),"=r"(r[31])
      : "r"(addr));
}
#endif  // HAS_TCGEN05

// ---------------------------------------------------------------------------
// Unified GEMM, R9: 128x256 output tile (N=256 MMAs) to cut L2 traffic 25%.
// tcgen05 bf16x3 on sm_103a; FFMA2 fp32 fallback (2x 128-col halves) else.
// ---------------------------------------------------------------------------
#define A_TILE  (128 * 64 * 2)     // 16KB
#define B_TILE  (256 * 64 * 2)     // 32KB
#define G_BUF   (2 * A_TILE + 2 * B_TILE)   // 96KB: Ah,Al,Bh,Bl
#define G_SMEM  (1024 + 2 * G_BUF) // ~193KB

__global__ void __launch_bounds__(256) gemm_kernel(
    const __nv_bfloat16* __restrict__ Ah, const __nv_bfloat16* __restrict__ Al,
    const __nv_bfloat16* __restrict__ Bh, const __nv_bfloat16* __restrict__ Bl,
    const float* __restrict__ Af, const float* __restrict__ Bf,
    float* __restrict__ C, int M, int N, int K) {
  extern __shared__ char smem[];
  const int tid = threadIdx.x;
  const int brow = blockIdx.y * 128, bcol0 = blockIdx.x * 256;

#if HAS_TCGEN05
  const unsigned sb = smem_u32(smem);
  const int wid = tid >> 5, lid = tid & 31;
  const int NKT = K >> 6;
  const unsigned mb0 = sb + 16, mb1 = sb + 24;
  const unsigned tiles = sb + 1024;

  if (tid == 0) { mbar_init(mb0, 1); mbar_init(mb1, 1); }
  if (wid == 0) { tmem_alloc(sb, 256); tmem_relinquish(); }
  __syncthreads();
  unsigned tmem;
  asm volatile("ld.shared.b32 %0, [%1];" : "=r"(tmem) : "r"(sb));

  auto stage1 = [&](unsigned dstbase, const __nv_bfloat16* src, int nrows) {
    const int lines = nrows * 8;
#pragma unroll 8
    for (int i = tid; i < lines; i += 256) {
      int r = i >> 3, c = i & 7;
      cp_async16(dstbase + SWZ128(r * 128 + c * 16), src + (size_t)r * K + c * 8);
    }
  };
  auto stage = [&](int buf, int kt) {
    unsigned base = tiles + buf * G_BUF;
    stage1(base,                       Ah + (size_t)brow * K + kt * 64, 128);
    stage1(base + A_TILE,              Al + (size_t)brow * K + kt * 64, 128);
    stage1(base + 2 * A_TILE,          Bh + (size_t)bcol0 * K + kt * 64, 256);
    stage1(base + 2 * A_TILE + B_TILE, Bl + (size_t)bcol0 * K + kt * 64, 256);
  };

  stage(0, 0);
  CP_COMMIT();
  int ph0 = 0, ph1 = 0;

  for (int kt = 0; kt < NKT; kt++) {
    const int buf = kt & 1;
    if (kt > 0) {
      if (((kt - 1) & 1) == 0) { mbar_wait(mb0, ph0 & 1); ph0++; }
      else                     { mbar_wait(mb1, ph1 & 1); ph1++; }
    }
    if (kt + 1 < NKT) { stage(buf ^ 1, kt + 1); CP_COMMIT(); CP_WAIT(1); }
    else              { CP_WAIT(0); }
    __syncthreads();

    if (wid == 0 && elect_one()) {
      asm volatile("fence.proxy.async.shared::cta;" ::: "memory");
      unsigned base = tiles + buf * G_BUF;
      u64 dAh = make_desc(base),              dAl = make_desc(base + A_TILE);
      u64 dBh = make_desc(base + 2 * A_TILE), dBl = make_desc(base + 2 * A_TILE + B_TILE);
      u64 da[3] = {dAh, dAl, dAh};
      u64 db[3] = {dBh, dBh, dBl};
#pragma unroll
      for (int p = 0; p < 3; p++)
#pragma unroll
        for (int ks = 0; ks < 4; ks++)
          mma_f16_ss(tmem, da[p] + ks * 2, db[p] + ks * 2, GEMM_IDESC,
                     !(kt == 0 && p == 0 && ks == 0));
      tc_commit(buf == 0 ? mb0 : mb1);
    }
  }
  if (((NKT - 1) & 1) == 0) { mbar_wait(mb0, ph0 & 1); }
  else                      { mbar_wait(mb1, ph1 & 1); }
  TC_FENCE_AFTER();

  if (wid < 4) {
    const size_t row = (size_t)brow + wid * 32 + lid;
#pragma unroll
    for (int cb = 0; cb < 256; cb += 32) {
      unsigned r[32];
      tmem_ld32(r, tmem + cb);
      TC_WAIT_LD();
      float* dst = &C[row * N + bcol0 + cb];
#pragma unroll
      for (int c = 0; c < 32; c += 4)
        *(float4*)&dst[c] = make_float4(__uint_as_float(r[c]), __uint_as_float(r[c+1]),
                                        __uint_as_float(r[c+2]), __uint_as_float(r[c+3]));
    }
  }
  __syncthreads();
  if (wid == 0) tmem_dealloc(tmem, 256);

#else  // fallback: fp32 FFMA2 SGEMM over the two 128-col halves
  float (*As)[16][132] = reinterpret_cast<float(*)[16][132]>(smem);
  float (*Bs)[16][132] = reinterpret_cast<float(*)[16][132]>(smem + 2 * 16 * 132 * 4);
  const int ty = tid >> 4, tx = tid & 15;
  const int ar0 = tid >> 2,          ac0 = (tid & 3) * 4;
  const int ar1 = (tid + 256) >> 2,  ac1 = ((tid + 256) & 3) * 4;
  const int br0 = tid >> 5,          bc0 = (tid & 31) * 4;
  const int br1 = (tid + 256) >> 5,  bc1 = ((tid + 256) & 31) * 4;

  for (int half = 0; half < 2; half++) {
    const int bcol = bcol0 + half * 128;
    __syncthreads();
    u64 acc2[8][4];
#pragma unroll
    for (int i = 0; i < 8; i++)
#pragma unroll
      for (int j = 0; j < 4; j++) acc2[i][j] = 0ull;

    {
      float4 a0 = *(const float4*)&Af[(size_t)(brow + ar0) * K + ac0];
      float4 a1 = *(const float4*)&Af[(size_t)(brow + ar1) * K + ac1];
      As[0][ac0 + 0][ar0] = a0.x; As[0][ac0 + 1][ar0] = a0.y;
      As[0][ac0 + 2][ar0] = a0.z; As[0][ac0 + 3][ar0] = a0.w;
      As[0][ac1 + 0][ar1] = a1.x; As[0][ac1 + 1][ar1] = a1.y;
      As[0][ac1 + 2][ar1] = a1.z; As[0][ac1 + 3][ar1] = a1.w;
      *(float4*)&Bs[0][br0][bc0] = *(const float4*)&Bf[(size_t)br0 * N + bcol + bc0];
      *(float4*)&Bs[0][br1][bc1] = *(const float4*)&Bf[(size_t)br1 * N + bcol + bc1];
    }
    __syncthreads();

    int buf = 0;
    for (int k0 = 0; k0 < K; k0 += 16) {
      const bool has_next = (k0 + 16) < K;
      float4 pa0, pa1, pb0, pb1;
      if (has_next) {
        pa0 = *(const float4*)&Af[(size_t)(brow + ar0) * K + k0 + 16 + ac0];
        pa1 = *(const float4*)&Af[(size_t)(brow + ar1) * K + k0 + 16 + ac1];
        pb0 = *(const float4*)&Bf[(size_t)(k0 + 16 + br0) * N + bcol + bc0];
        pb1 = *(const float4*)&Bf[(size_t)(k0 + 16 + br1) * N + bcol + bc1];
      }
#pragma unroll
      for (int kk = 0; kk < 16; kk++) {
        float a[8];
        *(float4*)&a[0] = *(float4*)&As[buf][kk][ty * 8];
        *(float4*)&a[4] = *(float4*)&As[buf][kk][ty * 8 + 4];
        u64 b2[4];
        *(ulonglong2*)&b2[0] = *(ulonglong2*)&Bs[buf][kk][tx * 4];
        *(ulonglong2*)&b2[2] = *(ulonglong2*)&Bs[buf][kk][64 + tx * 4];
        u64 ad[8];
#pragma unroll
        for (int i = 0; i < 8; i++) ad[i] = fpack2(a[i], a[i]);
#pragma unroll
        for (int i = 0; i < 8; i++)
#pragma unroll
          for (int j = 0; j < 4; j++) acc2[i][j] = ffma2(ad[i], b2[j], acc2[i][j]);
      }
      if (has_next) {
        int nb = buf ^ 1;
        As[nb][ac0 + 0][ar0] = pa0.x; As[nb][ac0 + 1][ar0] = pa0.y;
        As[nb][ac0 + 2][ar0] = pa0.z; As[nb][ac0 + 3][ar0] = pa0.w;
        As[nb][ac1 + 0][ar1] = pa1.x; As[nb][ac1 + 1][ar1] = pa1.y;
        As[nb][ac1 + 2][ar1] = pa1.z; As[nb][ac1 + 3][ar1] = pa1.w;
        *(float4*)&Bs[nb][br0][bc0] = pb0;
        *(float4*)&Bs[nb][br1][bc1] = pb1;
        __syncthreads();
        buf = nb;
      }
    }
#pragma unroll
    for (int i = 0; i < 8; i++) {
      size_t r = (size_t)(brow + ty * 8 + i) * N + bcol;
      *(ulonglong2*)&C[r + tx * 4]      = make_ulonglong2(acc2[i][0], acc2[i][1]);
      *(ulonglong2*)&C[r + 64 + tx * 4] = make_ulonglong2(acc2[i][2], acc2[i][3]);
    }
  }
#endif
}

// ---------------------------------------------------------------------------
__global__ void __launch_bounds__(256) split_kernel(
    const float* __restrict__ src, __nv_bfloat16* __restrict__ h,
    __nv_bfloat16* __restrict__ l, int n4) {
  int i = blockIdx.x * 256 + threadIdx.x;
  if (i >= n4) return;
  float4 v = ((const float4*)src)[i];
  __nv_bfloat16 h0 = __float2bfloat16_rn(v.x), h1 = __float2bfloat16_rn(v.y);
  __nv_bfloat16 h2 = __float2bfloat16_rn(v.z), h3 = __float2bfloat16_rn(v.w);
  __nv_bfloat16 l0 = __float2bfloat16_rn(v.x - __bfloat162float(h0));
  __nv_bfloat16 l1 = __float2bfloat16_rn(v.y - __bfloat162float(h1));
  __nv_bfloat16 l2 = __float2bfloat16_rn(v.z - __bfloat162float(h2));
  __nv_bfloat16 l3 = __float2bfloat16_rn(v.w - __bfloat162float(h3));
  ((__nv_bfloat162*)h)[i * 2]     = __nv_bfloat162(h0, h1);
  ((__nv_bfloat162*)h)[i * 2 + 1] = __nv_bfloat162(h2, h3);
  ((__nv_bfloat162*)l)[i * 2]     = __nv_bfloat162(l0, l1);
  ((__nv_bfloat162*)l)[i * 2 + 1] = __nv_bfloat162(l2, l3);
}

__global__ void __launch_bounds__(256) splitT_kernel(
    const float* __restrict__ w, __nv_bfloat16* __restrict__ h,
    __nv_bfloat16* __restrict__ l, int K, int N) {
  __shared__ float t[32][33];
  int n0 = blockIdx.x * 32, k0 = blockIdx.y * 32;
  int tx = threadIdx.x, ty = threadIdx.y;
#pragma unroll
  for (int i = 0; i < 32; i += 8)
    t[ty + i][tx] = w[(size_t)(k0 + ty + i) * N + n0 + tx];
  __syncthreads();
#pragma unroll
  for (int i = 0; i < 32; i += 8) {
    float v = t[tx][ty + i];
    __nv_bfloat16 hh = __float2bfloat16_rn(v);
    __nv_bfloat16 ll = __float2bfloat16_rn(v - __bfloat162float(hh));
    size_t o = (size_t)(n0 + ty + i) * K + k0 + tx;
    h[o] = hh; l[o] = ll;
  }
}

// ---------------------------------------------------------------------------
// Flash attention with RPE. R9: fully register-resident softmax.
// Scores stay in registers; row max/sum via shfl within the 16-lane row
// group; m/l/cf are per-thread registers. Ss buffer eliminated (smem 80KB).
// ---------------------------------------------------------------------------
__device__ __forceinline__ int swz(int r, int kk) {
  return r * 64 + ((((kk >> 2) ^ (r >> 2)) & 15) << 2) + (kk & 3);
}

#define ATT_SMEM_FLOATS (3 * 64 * 64 + 128 * 64)
#define ATT_SMEM_BYTES  (ATT_SMEM_FLOATS * 4)

__global__ void __launch_bounds__(256, 2) attn_kernel(
    const float* __restrict__ qkv, const float* __restrict__ embk,
    const float* __restrict__ embv, float* __restrict__ y) {
  extern __shared__ float sm[];
  float* Qs  = sm;                  // 64 x 64 swizzled
  float* Ks  = sm + 64 * 64;        // 64 x 64 swizzled (K, then PT = P^T)
  float* Vs  = sm + 2 * 64 * 64;    // 64 x 64 swizzled
  float* Es  = sm + 3 * 64 * 64;    // 128 x 64 swizzled (embk then embv)

  const int tid = threadIdx.x;
  const int tb = gridDim.x - 1 - blockIdx.x;   // heavy blocks first
  const int h = blockIdx.y, b = blockIdx.z;
  const int t0 = tb * 64;
  const int ty = tid >> 4, tx = tid & 15;
  const int tloc = ty * 4;
  const int cloc = tx * 4;

  // Load Q tile (vectorized)
#pragma unroll
  for (int it = 0; it < 4; it++) {
    int g = it * 256 + tid;
    int t = g >> 4, kc = (g & 15) << 2;
    *(float4*)&Qs[swz(t, kc)] =
        *(const float4*)&qkv[(b * TSEQ + t0 + t) * (3 * CDIM) + h * 64 + kc];
  }

  float m_r[4], l_r[4];
#pragma unroll
  for (int i = 0; i < 4; i++) { m_r[i] = -1e30f; l_r[i] = 0.f; }

  u64 accO2[4][2];
#pragma unroll
  for (int i = 0; i < 4; i++) { accO2[i][0] = 0ull; accO2[i][1] = 0ull; }

  for (int sb = 0; sb <= tb; sb++) {
    const int s0 = sb * 64;
    const int diff = t0 - s0;
    __syncthreads();   // prior O-phase reads (Vs/Es/PT) done

    // stage K (pre-scaled) and V
#pragma unroll
    for (int it = 0; it < 4; it++) {
      int g = it * 256 + tid;
      int s = g >> 4, kc = (g & 15) << 2;
      const float* src = &qkv[(b * TSEQ + s0 + s) * (3 * CDIM) + h * 64 + kc];
      float4 kv = *(const float4*)(src + CDIM);
      float4 vv = *(const float4*)(src + 2 * CDIM);
      kv.x *= 0.125f; kv.y *= 0.125f; kv.z *= 0.125f; kv.w *= 0.125f;
      *(float4*)&Ks[swz(s, kc)] = kv;
      *(float4*)&Vs[swz(s, kc)] = vv;
    }
    // stage embk rows
#pragma unroll
    for (int it = 0; it < 8; it++) {
      int g = it * 256 + tid;
      int j = g >> 4, kc = (g & 15) << 2;
      int rel = diff - 63 + j;
      float4 v = make_float4(0.f, 0.f, 0.f, 0.f);
      if (rel >= 0 && rel < TSEQ) v = *(const float4*)&embk[rel * 64 + kc];
      *(float4*)&Es[swz(j, kc)] = v;
    }
    __syncthreads();

    // ---- S phase: S[t,s] = q . (k_scaled + embk[t-s]) ----
    u64 acc2[4][4];
#pragma unroll
    for (int i = 0; i < 4; i++)
#pragma unroll
      for (int j = 0; j < 4; j++) acc2[i][j] = 0ull;

    const int ebase = tloc - cloc + 60;
#pragma unroll 4
    for (int kk = 0; kk < 64; kk += 4) {
      ulonglong2 qd[4], kd[4], ed[7];
#pragma unroll
      for (int i = 0; i < 4; i++) qd[i] = *(ulonglong2*)&Qs[swz(tloc + i, kk)];
#pragma unroll
      for (int j = 0; j < 4; j++) kd[j] = *(ulonglong2*)&Ks[swz(cloc + j, kk)];
#pragma unroll
      for (int m = 0; m < 7; m++) ed[m] = *(ulonglong2*)&Es[swz(ebase + m, kk)];
#pragma unroll
      for (int i = 0; i < 4; i++)
#pragma unroll
        for (int j = 0; j < 4; j++) {
          ulonglong2 e2 = ed[i - j + 3];
          acc2[i][j] = ffma2(qd[i].x, fadd2(kd[j].x, e2.x), acc2[i][j]);
          acc2[i][j] = ffma2(qd[i].y, fadd2(kd[j].y, e2.y), acc2[i][j]);
        }
    }
    // reduce pairs + causal mask into registers
    float sv[4][4];
#pragma unroll
    for (int i = 0; i < 4; i++)
#pragma unroll
      for (int j = 0; j < 4; j++) {
        float lo, hi; funpack2(lo, hi, acc2[i][j]);
        bool masked = (sb == tb) && (cloc + j > tloc + i);
        sv[i][j] = masked ? -1e30f : (lo + hi);
      }
    __syncthreads();   // all S-phase Ks reads done -> Ks reusable as PT

    // ---- register softmax: row group = 16 lanes (same ty, lane>>4) ----
    float c_r[4];
#pragma unroll
    for (int i = 0; i < 4; i++) {
      float mx = fmaxf(fmaxf(sv[i][0], sv[i][1]), fmaxf(sv[i][2], sv[i][3]));
      mx = fmaxf(mx, __shfl_xor_sync(0xffffffffu, mx, 1));
      mx = fmaxf(mx, __shfl_xor_sync(0xffffffffu, mx, 2));
      mx = fmaxf(mx, __shfl_xor_sync(0xffffffffu, mx, 4));
      mx = fmaxf(mx, __shfl_xor_sync(0xffffffffu, mx, 8));
      float mnew = fmaxf(m_r[i], mx);
      float s = 0.f;
#pragma unroll
      for (int j = 0; j < 4; j++) {
        float p = __expf(sv[i][j] - mnew);
        sv[i][j] = p;
        s += p;
      }
      s += __shfl_xor_sync(0xffffffffu, s, 1);
      s += __shfl_xor_sync(0xffffffffu, s, 2);
      s += __shfl_xor_sync(0xffffffffu, s, 4);
      s += __shfl_xor_sync(0xffffffffu, s, 8);
      c_r[i] = __expf(m_r[i] - mnew);
      m_r[i] = mnew;
      l_r[i] = l_r[i] * c_r[i] + s;
    }
    // write P transposed into Ks: PT[s][t]
#pragma unroll
    for (int i = 0; i < 4; i++)
#pragma unroll
      for (int j = 0; j < 4; j++)
        Ks[swz(cloc + j, tloc + i)] = sv[i][j];
    // stage embv rows (Es reuse)
#pragma unroll
    for (int it = 0; it < 8; it++) {
      int g = it * 256 + tid;
      int j = g >> 4, kc = (g & 15) << 2;
      int rel = diff - 63 + j;
      float4 v = make_float4(0.f, 0.f, 0.f, 0.f);
      if (rel >= 0 && rel < TSEQ) v = *(const float4*)&embv[rel * 64 + kc];
      *(float4*)&Es[swz(j, kc)] = v;
    }
    __syncthreads();

    // ---- O phase: O[t,e] += P[t,s] * (V[s,e] + embv[t-s][e]) ----
#pragma unroll
    for (int i = 0; i < 4; i++) {
      u64 cd = fpack2(c_r[i], c_r[i]);
      accO2[i][0] = fmul2(accO2[i][0], cd);
      accO2[i][1] = fmul2(accO2[i][1], cd);
    }
    ulonglong2 ew0 = *(ulonglong2*)&Es[swz(tloc + 0, cloc)];
    ulonglong2 ew1 = *(ulonglong2*)&Es[swz(tloc + 1, cloc)];
    ulonglong2 ew2 = *(ulonglong2*)&Es[swz(tloc + 2, cloc)];
    ulonglong2 ew3 = *(ulonglong2*)&Es[swz(tloc + 3, cloc)];
#pragma unroll 4
    for (int s5 = 0; s5 < 64; s5++) {
      const int s = 63 - s5;
      ulonglong2 vd = *(ulonglong2*)&Vs[swz(s, cloc)];
      float4 p4 = *(float4*)&Ks[swz(s, tloc)];   // PT broadcast
      u64 pd;
      pd = fpack2(p4.x, p4.x);
      accO2[0][0] = ffma2(pd, fadd2(vd.x, ew0.x), accO2[0][0]);
      accO2[0][1] = ffma2(pd, fadd2(vd.y, ew0.y), accO2[0][1]);
      pd = fpack2(p4.y, p4.y);
      accO2[1][0] = ffma2(pd, fadd2(vd.x, ew1.x), accO2[1][0]);
      accO2[1][1] = ffma2(pd, fadd2(vd.y, ew1.y), accO2[1][1]);
      pd = fpack2(p4.z, p4.z);
      accO2[2][0] = ffma2(pd, fadd2(vd.x, ew2.x), accO2[2][0]);
      accO2[2][1] = ffma2(pd, fadd2(vd.y, ew2.y), accO2[2][1]);
      pd = fpack2(p4.w, p4.w);
      accO2[3][0] = ffma2(pd, fadd2(vd.x, ew3.x), accO2[3][0]);
      accO2[3][1] = ffma2(pd, fadd2(vd.y, ew3.y), accO2[3][1]);
      ew0 = ew1; ew1 = ew2; ew2 = ew3;
      ew3 = *(ulonglong2*)&Es[swz(tloc + 4 + s5, cloc)];
    }
  }

  // epilogue
#pragma unroll
  for (int i = 0; i < 4; i++) {
    float linv = 1.f / l_r[i];
    float o[4];
    funpack2(o[0], o[1], accO2[i][0]);
    funpack2(o[2], o[3], accO2[i][1]);
    float4 ov = make_float4(o[0] * linv, o[1] * linv, o[2] * linv, o[3] * linv);
    *(float4*)&y[(b * TSEQ + t0 + tloc + i) * CDIM + h * 64 + cloc] = ov;
  }
}

// ---------------------------------------------------------------------------
extern "C" void kernel_launch(void* const* d_in, const int* in_sizes, int n_in,
                              void* d_out, int out_size) {
  const float* x      = (const float*)d_in[0];
  const float* w_attn = (const float*)d_in[1];
  const float* w_proj = (const float*)d_in[2];
  const float* embk   = (const float*)d_in[3];
  const float* embv   = (const float*)d_in[4];
  float* out = (float*)d_out;

  float *qkv, *y;
  __nv_bfloat16 *xh, *xl, *wah, *wal, *wph, *wpl, *yh, *yl;
  cudaGetSymbolAddress((void**)&qkv, g_qkv);
  cudaGetSymbolAddress((void**)&y,   g_y);
  cudaGetSymbolAddress((void**)&xh,  g_xh);  cudaGetSymbolAddress((void**)&xl, g_xl);
  cudaGetSymbolAddress((void**)&wah, g_wah); cudaGetSymbolAddress((void**)&wal, g_wal);
  cudaGetSymbolAddress((void**)&wph, g_wph); cudaGetSymbolAddress((void**)&wpl, g_wpl);
  cudaGetSymbolAddress((void**)&yh,  g_yh);  cudaGetSymbolAddress((void**)&yl, g_yl);

  const int M = BSZ * TSEQ;
  const int n4 = M * CDIM / 4;

  split_kernel<<<(n4 + 255) / 256, 256>>>(x, xh, xl, n4);
  splitT_kernel<<<dim3(3 * CDIM / 32, CDIM / 32), dim3(32, 8)>>>(w_attn, wah, wal,
                                                                 CDIM, 3 * CDIM);
  splitT_kernel<<<dim3(CDIM / 32, CDIM / 32), dim3(32, 8)>>>(w_proj, wph, wpl,
                                                             CDIM, CDIM);

  cudaFuncSetAttribute(gemm_kernel,
                       cudaFuncAttributeMaxDynamicSharedMemorySize, G_SMEM);
  // QKV: [4096,1024] @ [1024,3072]
  gemm_kernel<<<dim3(3 * CDIM / 256, M / 128), 256, G_SMEM>>>(
      xh, xl, wah, wal, x, w_attn, qkv, M, 3 * CDIM, CDIM);

  cudaFuncSetAttribute(attn_kernel, cudaFuncAttributeMaxDynamicSharedMemorySize,
                       ATT_SMEM_BYTES);
  attn_kernel<<<dim3(TSEQ / 64, NHEAD, BSZ), 256, ATT_SMEM_BYTES>>>(qkv, embk,
                                                                    embv, y);

  split_kernel<<<(n4 + 255) / 256, 256>>>(y, yh, yl, n4);
  // Projection: [4096,1024] @ [1024,1024]
  gemm_kernel<<<dim3(CDIM / 256, M / 128), 256, G_SMEM>>>(
      yh, yl, wph, wpl, y, w_proj, out, M, CDIM, CDIM);
}

// round 11
// speedup vs baseline: 4.3752x; 1.0265x over previous
#include <cuda_runtime.h>
#include <cuda_bf16.h>
#include <math.h>

#define BSZ   4
#define TSEQ  1024
#define CDIM  1024
#define NHEAD 16
#define DHEAD 64

typedef unsigned long long u64;

#if defined(__CUDA_ARCH_FEAT_SM103_ALL) || \
    (defined(__CUDA_ARCH_SPECIFIC__) && (__CUDA_ARCH_SPECIFIC__ == 1030))
#define HAS_TCGEN05 1
#else
#define HAS_TCGEN05 0
#endif

// ---------------- scratch (allocation-free: __device__ globals) -------------
__device__ float g_qkv[BSZ * TSEQ * 3 * CDIM];
__device__ float g_G[BSZ * NHEAD * TSEQ * TSEQ];          // 268MB: q_t . embk[d]
__device__ __nv_bfloat16 g_xh[BSZ * TSEQ * CDIM], g_xl[BSZ * TSEQ * CDIM];
__device__ __nv_bfloat16 g_wah[3 * CDIM * CDIM], g_wal[3 * CDIM * CDIM]; // [N,K]
__device__ __nv_bfloat16 g_wph[CDIM * CDIM],     g_wpl[CDIM * CDIM];     // [N,K]
__device__ __nv_bfloat16 g_yh[BSZ * TSEQ * CDIM], g_yl[BSZ * TSEQ * CDIM];
__device__ __nv_bfloat16 g_qph[BSZ * NHEAD * TSEQ * DHEAD];  // packed Q hi
__device__ __nv_bfloat16 g_qpl[BSZ * NHEAD * TSEQ * DHEAD];  // packed Q lo
__device__ __nv_bfloat16 g_ebh[TSEQ * DHEAD], g_ebl[TSEQ * DHEAD];

// ---------------- packed f32x2 helpers --------------------------------------
__device__ __forceinline__ u64 ffma2(u64 a, u64 b, u64 c) {
  u64 d; asm("fma.rn.f32x2 %0, %1, %2, %3;" : "=l"(d) : "l"(a), "l"(b), "l"(c));
  return d;
}
__device__ __forceinline__ u64 fadd2(u64 a, u64 b) {
  u64 d; asm("add.rn.f32x2 %0, %1, %2;" : "=l"(d) : "l"(a), "l"(b));
  return d;
}
__device__ __forceinline__ u64 fmul2(u64 a, u64 b) {
  u64 d; asm("mul.rn.f32x2 %0, %1, %2;" : "=l"(d) : "l"(a), "l"(b));
  return d;
}
__device__ __forceinline__ u64 fpack2(float lo, float hi) {
  u64 d; asm("mov.b64 %0, {%1, %2};" : "=l"(d) : "f"(lo), "f"(hi));
  return d;
}
__device__ __forceinline__ void funpack2(float& lo, float& hi, u64 d) {
  asm("mov.b64 {%0, %1}, %2;" : "=f"(lo), "=f"(hi) : "l"(d));
}

// ---------------- generic plumbing ------------------------------------------
__device__ __forceinline__ unsigned smem_u32(const void* p) {
  unsigned a;
  asm("{ .reg .u64 t; cvta.to.shared.u64 t, %1; cvt.u32.u64 %0, t; }"
      : "=r"(a) : "l"(p));
  return a;
}
__device__ __forceinline__ unsigned elect_one() {
  unsigned p;
  asm volatile("{ .reg .pred P; elect.sync _|P, 0xFFFFFFFF; selp.b32 %0,1,0,P; }"
               : "=r"(p));
  return p;
}
__device__ __forceinline__ void cp_async16(unsigned dst, const void* src) {
  asm volatile("cp.async.cg.shared.global [%0], [%1], 16;"
               :: "r"(dst), "l"(src) : "memory");
}
#define CP_COMMIT() asm volatile("cp.async.commit_group;" ::: "memory")
#define CP_WAIT(n)  asm volatile("cp.async.wait_group %0;" :: "n"(n) : "memory")

__device__ __forceinline__ void mbar_init(unsigned a, unsigned cnt) {
  asm volatile("mbarrier.init.shared.b64 [%0], %1;" :: "r"(a), "r"(cnt) : "memory");
}
__device__ __forceinline__ void mbar_wait(unsigned a, unsigned phase) {
  asm volatile(
      "{\n\t.reg .pred P;\n\t"
      "W_%=:\n\t"
      "mbarrier.try_wait.parity.acquire.cta.shared::cta.b64 P, [%0], %1, 0x989680;\n\t"
      "@!P bra W_%=;\n\t}"
      :: "r"(a), "r"(phase) : "memory");
}

#define SWZ128(o) ((o) ^ (((o) >> 3) & 0x70))
__device__ __forceinline__ u64 make_desc(unsigned addr) {
  const u64 base = (2ull << 61) | (1ull << 46) | (64ull << 32) | (1ull << 16);
  return base | ((u64)(addr >> 4) & 0x3FFF);
}
// idesc: c=F32, a=BF16, b=BF16, M=128, N=256
#define GEMM_IDESC ((1u<<4)|(1u<<7)|(1u<<10)|((256u/8)<<17)|((128u/16)<<24))

// ---------------- tcgen05 wrappers (sm_103a pass only) ----------------------
#if HAS_TCGEN05
__device__ __forceinline__ void tmem_alloc(unsigned smem_dst, unsigned ncols) {
  asm volatile("tcgen05.alloc.cta_group::1.sync.aligned.shared::cta.b32 [%0], %1;"
               :: "r"(smem_dst), "r"(ncols) : "memory");
}
__device__ __forceinline__ void tmem_dealloc(unsigned tmem, unsigned ncols) {
  asm volatile("tcgen05.dealloc.cta_group::1.sync.aligned.b32 %0, %1;"
               :: "r"(tmem), "r"(ncols));
}
__device__ __forceinline__ void tmem_relinquish() {
  asm volatile("tcgen05.relinquish_alloc_permit.cta_group::1.sync.aligned;");
}
__device__ __forceinline__ void tc_commit(unsigned mbar) {
  asm volatile(
      "tcgen05.commit.cta_group::1.mbarrier::arrive::one.shared::cluster.b64 [%0];"
      :: "r"(mbar) : "memory");
}
#define TC_FENCE_AFTER()  asm volatile("tcgen05.fence::after_thread_sync;" ::: "memory")
#define TC_WAIT_LD()      asm volatile("tcgen05.wait::ld.sync.aligned;" ::: "memory")

__device__ __forceinline__ void mma_f16_ss(unsigned d_tmem, u64 a_desc, u64 b_desc,
                                           unsigned idesc, unsigned enable) {
  asm volatile(
      "{\n\t.reg .pred p;\n\tsetp.ne.u32 p, %4, 0;\n\t"
      "tcgen05.mma.cta_group::1.kind::f16 [%0], %1, %2, %3, {%5,%5,%5,%5}, p;\n\t}"
      :: "r"(d_tmem), "l"(a_desc), "l"(b_desc), "r"(idesc), "r"(enable), "r"(0u)
      : "memory");
}
__device__ __forceinline__ void tmem_ld32(unsigned* r, unsigned addr) {
  asm volatile(
      "tcgen05.ld.sync.aligned.32x32b.x32.b32 "
      "{%0,%1,%2,%3,%4,%5,%6,%7,%8,%9,%10,%11,%12,%13,%14,%15,"
      "%16,%17,%18,%19,%20,%21,%22,%23,%24,%25,%26,%27,%28,%29,%30,%31}, [%32];"
      : "=r"(r[0]),"=r"(r[1]),"=r"(r[2]),"=r"(r[3]),"=r"(r[4]),"=r"(r[5]),
        "=r"(r[6]),"=r"(r[7]),"=r"(r[8]),"=r"(r[9]),"=r"(r[10]),"=r"(r[11]),
        "=r"(r[12]),"=r"(r[13]),"=r"(r[14]),"=r"(r[15]),"=r"(r[16]),"=r"(r[17]),
        "=r"(r[18]),"=r"(r[19]),"=r"(r[20]),"=r"(r[21]),"=r"(r[22]),"=r"(r[23]),
        "=r"(r[24]),"=r"(r[25]),"=r"(r[26]),"=r"(r[27]),"=r"(r[28]),"=r"(r[29]),
        "=r"(r[30]),"=r"(r[31])
      : "r"(addr));
}
#endif  // HAS_TCGEN05

// ---------------------------------------------------------------------------
// Unified GEMM (R9 design, unchanged): 128x256 tile, tcgen05 bf16x3 on
// sm_103a, FFMA2 fp32 fallback otherwise. Works for NKT=1 (K=64) too.
// ---------------------------------------------------------------------------
#define A_TILE  (128 * 64 * 2)
#define B_TILE  (256 * 64 * 2)
#define G_BUF   (2 * A_TILE + 2 * B_TILE)
#define G_SMEM  (1024 + 2 * G_BUF)

__global__ void __launch_bounds__(256) gemm_kernel(
    const __nv_bfloat16* __restrict__ Ah, const __nv_bfloat16* __restrict__ Al,
    const __nv_bfloat16* __restrict__ Bh, const __nv_bfloat16* __restrict__ Bl,
    const float* __restrict__ Af, const float* __restrict__ Bf,
    float* __restrict__ C, int M, int N, int K) {
  extern __shared__ char smem[];
  const int tid = threadIdx.x;
  const int brow = blockIdx.y * 128, bcol0 = blockIdx.x * 256;

#if HAS_TCGEN05
  const unsigned sb = smem_u32(smem);
  const int wid = tid >> 5, lid = tid & 31;
  const int NKT = K >> 6;
  const unsigned mb0 = sb + 16, mb1 = sb + 24;
  const unsigned tiles = sb + 1024;

  if (tid == 0) { mbar_init(mb0, 1); mbar_init(mb1, 1); }
  if (wid == 0) { tmem_alloc(sb, 256); tmem_relinquish(); }
  __syncthreads();
  unsigned tmem;
  asm volatile("ld.shared.b32 %0, [%1];" : "=r"(tmem) : "r"(sb));

  auto stage1 = [&](unsigned dstbase, const __nv_bfloat16* src, int nrows) {
    const int lines = nrows * 8;
#pragma unroll 8
    for (int i = tid; i < lines; i += 256) {
      int r = i >> 3, c = i & 7;
      cp_async16(dstbase + SWZ128(r * 128 + c * 16), src + (size_t)r * K + c * 8);
    }
  };
  auto stage = [&](int buf, int kt) {
    unsigned base = tiles + buf * G_BUF;
    stage1(base,                       Ah + (size_t)brow * K + kt * 64, 128);
    stage1(base + A_TILE,              Al + (size_t)brow * K + kt * 64, 128);
    stage1(base + 2 * A_TILE,          Bh + (size_t)bcol0 * K + kt * 64, 256);
    stage1(base + 2 * A_TILE + B_TILE, Bl + (size_t)bcol0 * K + kt * 64, 256);
  };

  stage(0, 0);
  CP_COMMIT();
  int ph0 = 0, ph1 = 0;

  for (int kt = 0; kt < NKT; kt++) {
    const int buf = kt & 1;
    if (kt > 0) {
      if (((kt - 1) & 1) == 0) { mbar_wait(mb0, ph0 & 1); ph0++; }
      else                     { mbar_wait(mb1, ph1 & 1); ph1++; }
    }
    if (kt + 1 < NKT) { stage(buf ^ 1, kt + 1); CP_COMMIT(); CP_WAIT(1); }
    else              { CP_WAIT(0); }
    __syncthreads();

    if (wid == 0 && elect_one()) {
      asm volatile("fence.proxy.async.shared::cta;" ::: "memory");
      unsigned base = tiles + buf * G_BUF;
      u64 dAh = make_desc(base),              dAl = make_desc(base + A_TILE);
      u64 dBh = make_desc(base + 2 * A_TILE), dBl = make_desc(base + 2 * A_TILE + B_TILE);
      u64 da[3] = {dAh, dAl, dAh};
      u64 db[3] = {dBh, dBh, dBl};
#pragma unroll
      for (int p = 0; p < 3; p++)
#pragma unroll
        for (int ks = 0; ks < 4; ks++)
          mma_f16_ss(tmem, da[p] + ks * 2, db[p] + ks * 2, GEMM_IDESC,
                     !(kt == 0 && p == 0 && ks == 0));
      tc_commit(buf == 0 ? mb0 : mb1);
    }
  }
  if (((NKT - 1) & 1) == 0) { mbar_wait(mb0, ph0 & 1); }
  else                      { mbar_wait(mb1, ph1 & 1); }
  TC_FENCE_AFTER();

  if (wid < 4) {
    const size_t row = (size_t)brow + wid * 32 + lid;
#pragma unroll
    for (int cb = 0; cb < 256; cb += 32) {
      unsigned r[32];
      tmem_ld32(r, tmem + cb);
      TC_WAIT_LD();
      float* dst = &C[row * N + bcol0 + cb];
#pragma unroll
      for (int c = 0; c < 32; c += 4)
        *(float4*)&dst[c] = make_float4(__uint_as_float(r[c]), __uint_as_float(r[c+1]),
                                        __uint_as_float(r[c+2]), __uint_as_float(r[c+3]));
    }
  }
  __syncthreads();
  if (wid == 0) tmem_dealloc(tmem, 256);

#else  // fallback: fp32 FFMA2 SGEMM over the two 128-col halves
  float (*As)[16][132] = reinterpret_cast<float(*)[16][132]>(smem);
  float (*Bs)[16][132] = reinterpret_cast<float(*)[16][132]>(smem + 2 * 16 * 132 * 4);
  const int ty = tid >> 4, tx = tid & 15;
  const int ar0 = tid >> 2,          ac0 = (tid & 3) * 4;
  const int ar1 = (tid + 256) >> 2,  ac1 = ((tid + 256) & 3) * 4;
  const int br0 = tid >> 5,          bc0 = (tid & 31) * 4;
  const int br1 = (tid + 256) >> 5,  bc1 = ((tid + 256) & 31) * 4;

  for (int half = 0; half < 2; half++) {
    const int bcol = bcol0 + half * 128;
    __syncthreads();
    u64 acc2[8][4];
#pragma unroll
    for (int i = 0; i < 8; i++)
#pragma unroll
      for (int j = 0; j < 4; j++) acc2[i][j] = 0ull;

    {
      float4 a0 = *(const float4*)&Af[(size_t)(brow + ar0) * K + ac0];
      float4 a1 = *(const float4*)&Af[(size_t)(brow + ar1) * K + ac1];
      As[0][ac0 + 0][ar0] = a0.x; As[0][ac0 + 1][ar0] = a0.y;
      As[0][ac0 + 2][ar0] = a0.z; As[0][ac0 + 3][ar0] = a0.w;
      As[0][ac1 + 0][ar1] = a1.x; As[0][ac1 + 1][ar1] = a1.y;
      As[0][ac1 + 2][ar1] = a1.z; As[0][ac1 + 3][ar1] = a1.w;
      *(float4*)&Bs[0][br0][bc0] = *(const float4*)&Bf[(size_t)br0 * N + bcol + bc0];
      *(float4*)&Bs[0][br1][bc1] = *(const float4*)&Bf[(size_t)br1 * N + bcol + bc1];
    }
    __syncthreads();

    int buf = 0;
    for (int k0 = 0; k0 < K; k0 += 16) {
      const bool has_next = (k0 + 16) < K;
      float4 pa0, pa1, pb0, pb1;
      if (has_next) {
        pa0 = *(const float4*)&Af[(size_t)(brow + ar0) * K + k0 + 16 + ac0];
        pa1 = *(const float4*)&Af[(size_t)(brow + ar1) * K + k0 + 16 + ac1];
        pb0 = *(const float4*)&Bf[(size_t)(k0 + 16 + br0) * N + bcol + bc0];
        pb1 = *(const float4*)&Bf[(size_t)(k0 + 16 + br1) * N + bcol + bc1];
      }
#pragma unroll
      for (int kk = 0; kk < 16; kk++) {
        float a[8];
        *(float4*)&a[0] = *(float4*)&As[buf][kk][ty * 8];
        *(float4*)&a[4] = *(float4*)&As[buf][kk][ty * 8 + 4];
        u64 b2[4];
        *(ulonglong2*)&b2[0] = *(ulonglong2*)&Bs[buf][kk][tx * 4];
        *(ulonglong2*)&b2[2] = *(ulonglong2*)&Bs[buf][kk][64 + tx * 4];
        u64 ad[8];
#pragma unroll
        for (int i = 0; i < 8; i++) ad[i] = fpack2(a[i], a[i]);
#pragma unroll
        for (int i = 0; i < 8; i++)
#pragma unroll
          for (int j = 0; j < 4; j++) acc2[i][j] = ffma2(ad[i], b2[j], acc2[i][j]);
      }
      if (has_next) {
        int nb = buf ^ 1;
        As[nb][ac0 + 0][ar0] = pa0.x; As[nb][ac0 + 1][ar0] = pa0.y;
        As[nb][ac0 + 2][ar0] = pa0.z; As[nb][ac0 + 3][ar0] = pa0.w;
        As[nb][ac1 + 0][ar1] = pa1.x; As[nb][ac1 + 1][ar1] = pa1.y;
        As[nb][ac1 + 2][ar1] = pa1.z; As[nb][ac1 + 3][ar1] = pa1.w;
        *(float4*)&Bs[nb][br0][bc0] = pb0;
        *(float4*)&Bs[nb][br1][bc1] = pb1;
        __syncthreads();
        buf = nb;
      }
    }
#pragma unroll
    for (int i = 0; i < 8; i++) {
      size_t r = (size_t)(brow + ty * 8 + i) * N + bcol;
      *(ulonglong2*)&C[r + tx * 4]      = make_ulonglong2(acc2[i][0], acc2[i][1]);
      *(ulonglong2*)&C[r + 64 + tx * 4] = make_ulonglong2(acc2[i][2], acc2[i][3]);
    }
  }
#endif
}

// ---------------------------------------------------------------------------
__global__ void __launch_bounds__(256) split_kernel(
    const float* __restrict__ src, __nv_bfloat16* __restrict__ h,
    __nv_bfloat16* __restrict__ l, int n4) {
  int i = blockIdx.x * 256 + threadIdx.x;
  if (i >= n4) return;
  float4 v = ((const float4*)src)[i];
  __nv_bfloat16 h0 = __float2bfloat16_rn(v.x), h1 = __float2bfloat16_rn(v.y);
  __nv_bfloat16 h2 = __float2bfloat16_rn(v.z), h3 = __float2bfloat16_rn(v.w);
  __nv_bfloat16 l0 = __float2bfloat16_rn(v.x - __bfloat162float(h0));
  __nv_bfloat16 l1 = __float2bfloat16_rn(v.y - __bfloat162float(h1));
  __nv_bfloat16 l2 = __float2bfloat16_rn(v.z - __bfloat162float(h2));
  __nv_bfloat16 l3 = __float2bfloat16_rn(v.w - __bfloat162float(h3));
  ((__nv_bfloat162*)h)[i * 2]     = __nv_bfloat162(h0, h1);
  ((__nv_bfloat162*)h)[i * 2 + 1] = __nv_bfloat162(h2, h3);
  ((__nv_bfloat162*)l)[i * 2]     = __nv_bfloat162(l0, l1);
  ((__nv_bfloat162*)l)[i * 2 + 1] = __nv_bfloat162(l2, l3);
}

__global__ void __launch_bounds__(256) splitT_kernel(
    const float* __restrict__ w, __nv_bfloat16* __restrict__ h,
    __nv_bfloat16* __restrict__ l, int K, int N) {
  __shared__ float t[32][33];
  int n0 = blockIdx.x * 32, k0 = blockIdx.y * 32;
  int tx = threadIdx.x, ty = threadIdx.y;
#pragma unroll
  for (int i = 0; i < 32; i += 8)
    t[ty + i][tx] = w[(size_t)(k0 + ty + i) * N + n0 + tx];
  __syncthreads();
#pragma unroll
  for (int i = 0; i < 32; i += 8) {
    float v = t[tx][ty + i];
    __nv_bfloat16 hh = __float2bfloat16_rn(v);
    __nv_bfloat16 ll = __float2bfloat16_rn(v - __bfloat162float(hh));
    size_t o = (size_t)(n0 + ty + i) * K + k0 + tx;
    h[o] = hh; l[o] = ll;
  }
}

// Pack the Q part of qkv into [b*H+h][t][64] bf16 hi/lo (A operand for the
// G GEMM: G[bht, d] = q . embk[d]).
__global__ void __launch_bounds__(256) qpack_kernel(
    const float* __restrict__ qkv, __nv_bfloat16* __restrict__ qh,
    __nv_bfloat16* __restrict__ ql) {
  int idx = blockIdx.x * 256 + threadIdx.x;          // over 65536*16
  int row = idx >> 4;
  int dc = (idx & 15) << 2;
  int bh = row >> 10, t = row & 1023;
  int b = bh >> 4, hh = bh & 15;
  float4 v = *(const float4*)&qkv[((size_t)(b * TSEQ + t)) * (3 * CDIM) + hh * 64 + dc];
  __nv_bfloat16 h0 = __float2bfloat16_rn(v.x), h1 = __float2bfloat16_rn(v.y);
  __nv_bfloat16 h2 = __float2bfloat16_rn(v.z), h3 = __float2bfloat16_rn(v.w);
  __nv_bfloat16 l0 = __float2bfloat16_rn(v.x - __bfloat162float(h0));
  __nv_bfloat16 l1 = __float2bfloat16_rn(v.y - __bfloat162float(h1));
  __nv_bfloat16 l2 = __float2bfloat16_rn(v.z - __bfloat162float(h2));
  __nv_bfloat16 l3 = __float2bfloat16_rn(v.w - __bfloat162float(h3));
  size_t o = (size_t)row * 64 + dc;
  *(__nv_bfloat162*)&qh[o]     = __nv_bfloat162(h0, h1);
  *(__nv_bfloat162*)&qh[o + 2] = __nv_bfloat162(h2, h3);
  *(__nv_bfloat162*)&ql[o]     = __nv_bfloat162(l0, l1);
  *(__nv_bfloat162*)&ql[o + 2] = __nv_bfloat162(l2, l3);
}

// ---------------------------------------------------------------------------
// Flash attention with RPE. R10:
//  - score-side RPE comes from precomputed G[bht][d] (coalesced LDG gather);
//    no embk staging, no fadd2 in the S inner loop.
//  - Es buffer holds only embv, staged at tile top.
//  - O phase: software-prefetch vd/p4 one step ahead.
//  - epilogue writes yh/yl bf16 directly (proj consumes them).
// ---------------------------------------------------------------------------
__device__ __forceinline__ int swz(int r, int kk) {
  return r * 64 + ((((kk >> 2) ^ (r >> 2)) & 15) << 2) + (kk & 3);
}

#define ATT_SMEM_FLOATS (3 * 64 * 64 + 128 * 64)
#define ATT_SMEM_BYTES  (ATT_SMEM_FLOATS * 4)

__global__ void __launch_bounds__(256, 2) attn_kernel(
    const float* __restrict__ qkv, const float* __restrict__ G,
    const float* __restrict__ embv,
    __nv_bfloat16* __restrict__ yh, __nv_bfloat16* __restrict__ yl) {
  extern __shared__ float sm[];
  float* Qs  = sm;                  // 64 x 64 swizzled
  float* Ks  = sm + 64 * 64;        // 64 x 64 swizzled (K, then PT = P^T)
  float* Vs  = sm + 2 * 64 * 64;    // 64 x 64 swizzled
  float* Es  = sm + 3 * 64 * 64;    // 128 x 64 swizzled (embv)

  const int tid = threadIdx.x;
  const int tb = gridDim.x - 1 - blockIdx.x;   // heavy blocks first
  const int h = blockIdx.y, b = blockIdx.z;
  const int t0 = tb * 64;
  const int ty = tid >> 4, tx = tid & 15;
  const int tloc = ty * 4;
  const int cloc = tx * 4;

  // G row pointers for this thread's 4 rows
  const float* Grow[4];
#pragma unroll
  for (int i = 0; i < 4; i++)
    Grow[i] = G + (((size_t)(b * NHEAD + h) * TSEQ) + (t0 + tloc + i)) * TSEQ;

  // Load Q tile
#pragma unroll
  for (int it = 0; it < 4; it++) {
    int g = it * 256 + tid;
    int t = g >> 4, kc = (g & 15) << 2;
    *(float4*)&Qs[swz(t, kc)] =
        *(const float4*)&qkv[(b * TSEQ + t0 + t) * (3 * CDIM) + h * 64 + kc];
  }

  float m_r[4], l_r[4];
#pragma unroll
  for (int i = 0; i < 4; i++) { m_r[i] = -1e30f; l_r[i] = 0.f; }

  u64 accO2[4][2];
#pragma unroll
  for (int i = 0; i < 4; i++) { accO2[i][0] = 0ull; accO2[i][1] = 0ull; }

  for (int sb = 0; sb <= tb; sb++) {
    const int s0 = sb * 64;
    const int diff = t0 - s0;
    __syncthreads();   // prior O-phase reads done

    // stage K (pre-scaled), V, embv rows
#pragma unroll
    for (int it = 0; it < 4; it++) {
      int g = it * 256 + tid;
      int s = g >> 4, kc = (g & 15) << 2;
      const float* src = &qkv[(b * TSEQ + s0 + s) * (3 * CDIM) + h * 64 + kc];
      float4 kv = *(const float4*)(src + CDIM);
      float4 vv = *(const float4*)(src + 2 * CDIM);
      kv.x *= 0.125f; kv.y *= 0.125f; kv.z *= 0.125f; kv.w *= 0.125f;
      *(float4*)&Ks[swz(s, kc)] = kv;
      *(float4*)&Vs[swz(s, kc)] = vv;
    }
#pragma unroll
    for (int it = 0; it < 8; it++) {
      int g = it * 256 + tid;
      int j = g >> 4, kc = (g & 15) << 2;
      int rel = diff - 63 + j;
      float4 v = make_float4(0.f, 0.f, 0.f, 0.f);
      if (rel >= 0 && rel < TSEQ) v = *(const float4*)&embv[rel * 64 + kc];
      *(float4*)&Es[swz(j, kc)] = v;
    }
    // gather G band while staging is in flight (independent LDGs)
    float gv[4][4];
    if (sb < tb) {
#pragma unroll
      for (int i = 0; i < 4; i++) {
        int Di = diff + tloc + i - cloc;
#pragma unroll
        for (int j = 0; j < 4; j++) gv[i][j] = Grow[i][Di - j];
      }
    } else {
#pragma unroll
      for (int i = 0; i < 4; i++) {
        int Di = diff + tloc + i - cloc;
#pragma unroll
        for (int j = 0; j < 4; j++) {
          int d = Di - j;
          gv[i][j] = (d >= 0) ? Grow[i][d] : 0.f;
        }
      }
    }
    __syncthreads();

    // ---- S phase: S[t,s] = q . k_scaled  (+ G gathered afterwards) ----
    u64 acc2[4][4];
#pragma unroll
    for (int i = 0; i < 4; i++)
#pragma unroll
      for (int j = 0; j < 4; j++) acc2[i][j] = 0ull;

#pragma unroll 4
    for (int kk = 0; kk < 64; kk += 4) {
      ulonglong2 qd[4], kd[4];
#pragma unroll
      for (int i = 0; i < 4; i++) qd[i] = *(ulonglong2*)&Qs[swz(tloc + i, kk)];
#pragma unroll
      for (int j = 0; j < 4; j++) kd[j] = *(ulonglong2*)&Ks[swz(cloc + j, kk)];
#pragma unroll
      for (int i = 0; i < 4; i++)
#pragma unroll
        for (int j = 0; j < 4; j++) {
          acc2[i][j] = ffma2(qd[i].x, kd[j].x, acc2[i][j]);
          acc2[i][j] = ffma2(qd[i].y, kd[j].y, acc2[i][j]);
        }
    }
    // reduce pairs + G bias + causal mask into registers
    float sv[4][4];
#pragma unroll
    for (int i = 0; i < 4; i++)
#pragma unroll
      for (int j = 0; j < 4; j++) {
        float lo, hi; funpack2(lo, hi, acc2[i][j]);
        bool masked = (sb == tb) && (cloc + j > tloc + i);
        sv[i][j] = masked ? -1e30f : (lo + hi + gv[i][j]);
      }
    __syncthreads();   // all S-phase Ks reads done -> Ks reusable as PT

    // ---- register softmax (16-lane row groups) ----
    float c_r[4];
#pragma unroll
    for (int i = 0; i < 4; i++) {
      float mx = fmaxf(fmaxf(sv[i][0], sv[i][1]), fmaxf(sv[i][2], sv[i][3]));
      mx = fmaxf(mx, __shfl_xor_sync(0xffffffffu, mx, 1));
      mx = fmaxf(mx, __shfl_xor_sync(0xffffffffu, mx, 2));
      mx = fmaxf(mx, __shfl_xor_sync(0xffffffffu, mx, 4));
      mx = fmaxf(mx, __shfl_xor_sync(0xffffffffu, mx, 8));
      float mnew = fmaxf(m_r[i], mx);
      float s = 0.f;
#pragma unroll
      for (int j = 0; j < 4; j++) {
        float p = __expf(sv[i][j] - mnew);
        sv[i][j] = p;
        s += p;
      }
      s += __shfl_xor_sync(0xffffffffu, s, 1);
      s += __shfl_xor_sync(0xffffffffu, s, 2);
      s += __shfl_xor_sync(0xffffffffu, s, 4);
      s += __shfl_xor_sync(0xffffffffu, s, 8);
      c_r[i] = __expf(m_r[i] - mnew);
      m_r[i] = mnew;
      l_r[i] = l_r[i] * c_r[i] + s;
    }
    // write P transposed into Ks: PT[s][t]
#pragma unroll
    for (int i = 0; i < 4; i++)
#pragma unroll
      for (int j = 0; j < 4; j++)
        Ks[swz(cloc + j, tloc + i)] = sv[i][j];
    __syncthreads();

    // ---- O phase with 1-step prefetch ----
#pragma unroll
    for (int i = 0; i < 4; i++) {
      u64 cd = fpack2(c_r[i], c_r[i]);
      accO2[i][0] = fmul2(accO2[i][0], cd);
      accO2[i][1] = fmul2(accO2[i][1], cd);
    }
    ulonglong2 ew0 = *(ulonglong2*)&Es[swz(tloc + 0, cloc)];
    ulonglong2 ew1 = *(ulonglong2*)&Es[swz(tloc + 1, cloc)];
    ulonglong2 ew2 = *(ulonglong2*)&Es[swz(tloc + 2, cloc)];
    ulonglong2 ew3 = *(ulonglong2*)&Es[swz(tloc + 3, cloc)];
    ulonglong2 vd = *(ulonglong2*)&Vs[swz(63, cloc)];
    float4 p4 = *(float4*)&Ks[swz(63, tloc)];
#pragma unroll 4
    for (int s5 = 0; s5 < 64; s5++) {
      const int s = 63 - s5;
      ulonglong2 vdn = vd;
      float4 p4n = p4;
      if (s5 < 63) {
        vdn = *(ulonglong2*)&Vs[swz(s - 1, cloc)];
        p4n = *(float4*)&Ks[swz(s - 1, tloc)];
      }
      ulonglong2 ew3n = *(ulonglong2*)&Es[swz(tloc + 4 + s5, cloc)];
      u64 pd;
      pd = fpack2(p4.x, p4.x);
      accO2[0][0] = ffma2(pd, fadd2(vd.x, ew0.x), accO2[0][0]);
      accO2[0][1] = ffma2(pd, fadd2(vd.y, ew0.y), accO2[0][1]);
      pd = fpack2(p4.y, p4.y);
      accO2[1][0] = ffma2(pd, fadd2(vd.x, ew1.x), accO2[1][0]);
      accO2[1][1] = ffma2(pd, fadd2(vd.y, ew1.y), accO2[1][1]);
      pd = fpack2(p4.z, p4.z);
      accO2[2][0] = ffma2(pd, fadd2(vd.x, ew2.x), accO2[2][0]);
      accO2[2][1] = ffma2(pd, fadd2(vd.y, ew2.y), accO2[2][1]);
      pd = fpack2(p4.w, p4.w);
      accO2[3][0] = ffma2(pd, fadd2(vd.x, ew3.x), accO2[3][0]);
      accO2[3][1] = ffma2(pd, fadd2(vd.y, ew3.y), accO2[3][1]);
      ew0 = ew1; ew1 = ew2; ew2 = ew3; ew3 = ew3n;
      vd = vdn; p4 = p4n;
    }
  }

  // epilogue: normalize, split to bf16 hi/lo, write yh/yl
#pragma unroll
  for (int i = 0; i < 4; i++) {
    float linv = 1.f / l_r[i];
    float o[4];
    funpack2(o[0], o[1], accO2[i][0]);
    funpack2(o[2], o[3], accO2[i][1]);
    size_t off = ((size_t)(b * TSEQ + t0 + tloc + i)) * CDIM + h * 64 + cloc;
    __nv_bfloat16 hh[4], ll[4];
#pragma unroll
    for (int j = 0; j < 4; j++) {
      float v = o[j] * linv;
      hh[j] = __float2bfloat16_rn(v);
      ll[j] = __float2bfloat16_rn(v - __bfloat162float(hh[j]));
    }
    *(__nv_bfloat162*)&yh[off]     = __nv_bfloat162(hh[0], hh[1]);
    *(__nv_bfloat162*)&yh[off + 2] = __nv_bfloat162(hh[2], hh[3]);
    *(__nv_bfloat162*)&yl[off]     = __nv_bfloat162(ll[0], ll[1]);
    *(__nv_bfloat162*)&yl[off + 2] = __nv_bfloat162(ll[2], ll[3]);
  }
}

// ---------------------------------------------------------------------------
extern "C" void kernel_launch(void* const* d_in, const int* in_sizes, int n_in,
                              void* d_out, int out_size) {
  const float* x      = (const float*)d_in[0];
  const float* w_attn = (const float*)d_in[1];
  const float* w_proj = (const float*)d_in[2];
  const float* embk   = (const float*)d_in[3];
  const float* embv   = (const float*)d_in[4];
  float* out = (float*)d_out;

  float *qkv, *G;
  __nv_bfloat16 *xh, *xl, *wah, *wal, *wph, *wpl, *yh, *yl, *qph, *qpl, *ebh, *ebl;
  cudaGetSymbolAddress((void**)&qkv, g_qkv);
  cudaGetSymbolAddress((void**)&G,   g_G);
  cudaGetSymbolAddress((void**)&xh,  g_xh);  cudaGetSymbolAddress((void**)&xl, g_xl);
  cudaGetSymbolAddress((void**)&wah, g_wah); cudaGetSymbolAddress((void**)&wal, g_wal);
  cudaGetSymbolAddress((void**)&wph, g_wph); cudaGetSymbolAddress((void**)&wpl, g_wpl);
  cudaGetSymbolAddress((void**)&yh,  g_yh);  cudaGetSymbolAddress((void**)&yl, g_yl);
  cudaGetSymbolAddress((void**)&qph, g_qph); cudaGetSymbolAddress((void**)&qpl, g_qpl);
  cudaGetSymbolAddress((void**)&ebh, g_ebh); cudaGetSymbolAddress((void**)&ebl, g_ebl);

  const int M = BSZ * TSEQ;          // 4096
  const int n4 = M * CDIM / 4;

  split_kernel<<<(n4 + 255) / 256, 256>>>(x, xh, xl, n4);
  splitT_kernel<<<dim3(3 * CDIM / 32, CDIM / 32), dim3(32, 8)>>>(w_attn, wah, wal,
                                                                 CDIM, 3 * CDIM);
  splitT_kernel<<<dim3(CDIM / 32, CDIM / 32), dim3(32, 8)>>>(w_proj, wph, wpl,
                                                             CDIM, CDIM);
  split_kernel<<<(TSEQ * DHEAD / 4 + 255) / 256, 256>>>(embk, ebh, ebl,
                                                        TSEQ * DHEAD / 4);

  cudaFuncSetAttribute(gemm_kernel,
                       cudaFuncAttributeMaxDynamicSharedMemorySize, G_SMEM);
  // QKV: [4096,1024] @ [1024,3072]
  gemm_kernel<<<dim3(3 * CDIM / 256, M / 128), 256, G_SMEM>>>(
      xh, xl, wah, wal, x, w_attn, qkv, M, 3 * CDIM, CDIM);

  // pack Q and compute G = Qpack @ embk^T  (M=65536, N=1024, K=64)
  qpack_kernel<<<(BSZ * NHEAD * TSEQ * 16) / 256, 256>>>(qkv, qph, qpl);
  gemm_kernel<<<dim3(TSEQ / 256, (BSZ * NHEAD * TSEQ) / 128), 256, G_SMEM>>>(
      qph, qpl, ebh, ebl, qkv, w_attn, G, BSZ * NHEAD * TSEQ, TSEQ, DHEAD);

  cudaFuncSetAttribute(attn_kernel, cudaFuncAttributeMaxDynamicSharedMemorySize,
                       ATT_SMEM_BYTES);
  attn_kernel<<<dim3(TSEQ / 64, NHEAD, BSZ), 256, ATT_SMEM_BYTES>>>(qkv, G, embv,
                                                                    yh, yl);

  // Projection: [4096,1024] @ [1024,1024]
  gemm_kernel<<<dim3(CDIM / 256, M / 128), 256, G_SMEM>>>(
      yh, yl, wph, wpl, qkv, w_proj, out, M, CDIM, CDIM);
}